// round 2
// baseline (speedup 1.0000x reference)
#include <cuda_runtime.h>

// ---------------------------------------------------------------------------
// AttentionModule: out = gamma * (v @ softmax(q^T k)^T) + V
//   q = Wq Q + bq  [B,256,4096], k = Wk K + bk [B,256,4096], v = Wv V + bv [B,512,4096]
//   energy[b,n,m] = <q[b,:,n], k[b,:,m]>; attention = softmax over m
//   out[b,c,n] = gamma * sum_m v[b,c,m]*attention[b,n,m] + V[b,c,n]
//
// Strategy (round 1 — correct fp32 baseline, compute-bound on FMA pipe):
//   All GEMMs cast as row-major NN by storing k transposed (kt [N,CH]) and
//   energy transposed (eT[m][n] = energy[n][m]); softmax then runs over
//   COLUMNS of eT => coalesced row sweeps. Final GEMM is NN with fused
//   residual epilogue.
// ---------------------------------------------------------------------------

#define BM 128
#define BN 128
#define BK 8
#define NTHREADS 256

static const int B_ = 4, C_ = 512, CH_ = 256, N_ = 4096;

// Scratch (device globals: allocation inside kernel_launch is forbidden)
__device__ float g_q [4L * 256 * 4096];   // q  [B][CH][N]
__device__ float g_kt[4L * 4096 * 256];   // k^T [B][N][CH]
__device__ float g_v [4L * 512 * 4096];   // v  [B][C][N]
__device__ float g_e [4L * 4096 * 4096];  // energy^T / attention^T [B][N(m)][N(n)]

enum { F_TRANS = 1, F_BIAS = 2, F_RES = 4 };

// Generic row-major NN SGEMM: C[m,n] = sum_k A[m,k]*B[k,n] (+bias[m]) ;
// optional transposed store; optional residual epilogue gamma*acc + R[m,n].
// Batch via blockIdx.z strides. All of M,N,K assumed multiples of tile dims.
__global__ __launch_bounds__(NTHREADS)
void sgemm_kernel(const float* __restrict__ A, const float* __restrict__ B,
                  float* __restrict__ C, const float* __restrict__ bias,
                  const float* __restrict__ R, const float* __restrict__ gammap,
                  int M, int N, int K, int lda, int ldb, int ldc,
                  size_t sA, size_t sB, size_t sC, size_t sR, int flags)
{
    const int bz = blockIdx.z;
    A += (size_t)bz * sA;
    B += (size_t)bz * sB;
    C += (size_t)bz * sC;
    if (flags & F_RES) R += (size_t)bz * sR;

    __shared__ float As[BK][BM];
    __shared__ float Bs[BK][BN];

    const int tid = threadIdx.x;
    const int bm = blockIdx.y * BM;
    const int bn = blockIdx.x * BN;

    // A tile: BM x BK, each thread loads 4 consecutive k of one row (float4)
    const int ar = tid >> 1;            // 0..127
    const int ac = (tid & 1) << 2;      // 0 or 4
    // B tile: BK x BN, each thread loads 4 consecutive n (float4)
    const int br = tid >> 5;            // 0..7
    const int bc = (tid & 31) << 2;     // 0..124

    const int tx = tid & 15;            // column group
    const int ty = tid >> 4;            // row group

    float acc[8][8];
    #pragma unroll
    for (int i = 0; i < 8; i++)
        #pragma unroll
        for (int j = 0; j < 8; j++) acc[i][j] = 0.f;

    const float* Aptr = A + (size_t)(bm + ar) * lda + ac;
    const float* Bptr = B + (size_t)br * ldb + bn + bc;

    for (int k0 = 0; k0 < K; k0 += BK) {
        float4 a4 = *(const float4*)(Aptr + k0);
        float4 b4 = *(const float4*)(Bptr + (size_t)k0 * ldb);
        As[ac + 0][ar] = a4.x;
        As[ac + 1][ar] = a4.y;
        As[ac + 2][ar] = a4.z;
        As[ac + 3][ar] = a4.w;
        *(float4*)&Bs[br][bc] = b4;
        __syncthreads();

        #pragma unroll
        for (int kk = 0; kk < BK; kk++) {
            float ra[8], rb[8];
            *(float4*)&ra[0] = *(const float4*)&As[kk][ty * 4];
            *(float4*)&ra[4] = *(const float4*)&As[kk][64 + ty * 4];
            *(float4*)&rb[0] = *(const float4*)&Bs[kk][tx * 4];
            *(float4*)&rb[4] = *(const float4*)&Bs[kk][64 + tx * 4];
            #pragma unroll
            for (int i = 0; i < 8; i++)
                #pragma unroll
                for (int j = 0; j < 8; j++)
                    acc[i][j] += ra[i] * rb[j];
        }
        __syncthreads();
    }

    const float gamma = (flags & F_RES) ? *gammap : 0.f;

    #pragma unroll
    for (int i2 = 0; i2 < 2; i2++)
        #pragma unroll
        for (int ii = 0; ii < 4; ii++) {
            const int r = bm + i2 * 64 + ty * 4 + ii;
            const float bias_v = (flags & F_BIAS) ? bias[r] : 0.f;
            #pragma unroll
            for (int j2 = 0; j2 < 2; j2++) {
                const int cb = bn + j2 * 64 + tx * 4;
                if (flags & F_TRANS) {
                    #pragma unroll
                    for (int jj = 0; jj < 4; jj++)
                        C[(size_t)(cb + jj) * ldc + r] =
                            acc[i2 * 4 + ii][j2 * 4 + jj] + bias_v;
                } else if (flags & F_RES) {
                    float4 rv = *(const float4*)&R[(size_t)r * ldc + cb];
                    float4 o;
                    o.x = gamma * acc[i2 * 4 + ii][j2 * 4 + 0] + rv.x;
                    o.y = gamma * acc[i2 * 4 + ii][j2 * 4 + 1] + rv.y;
                    o.z = gamma * acc[i2 * 4 + ii][j2 * 4 + 2] + rv.z;
                    o.w = gamma * acc[i2 * 4 + ii][j2 * 4 + 3] + rv.w;
                    *(float4*)&C[(size_t)r * ldc + cb] = o;
                } else {
                    float4 o;
                    o.x = acc[i2 * 4 + ii][j2 * 4 + 0] + bias_v;
                    o.y = acc[i2 * 4 + ii][j2 * 4 + 1] + bias_v;
                    o.z = acc[i2 * 4 + ii][j2 * 4 + 2] + bias_v;
                    o.w = acc[i2 * 4 + ii][j2 * 4 + 3] + bias_v;
                    *(float4*)&C[(size_t)r * ldc + cb] = o;
                }
            }
        }
}

// Column softmax over eT [Nrows x ldn]: for each column n, softmax over rows m.
// Consecutive threads handle consecutive columns -> fully coalesced row sweeps.
__global__ void softmax_col_kernel(float* __restrict__ E, int Nrows, int ldn, size_t sE)
{
    float* Eb = E + (size_t)blockIdx.y * sE;
    const int n = blockIdx.x * blockDim.x + threadIdx.x;

    float mx = -1e30f, s = 0.f;
    for (int m = 0; m < Nrows; m++) {
        float x = Eb[(size_t)m * ldn + n];
        float nm = fmaxf(mx, x);
        s = s * __expf(mx - nm) + __expf(x - nm);
        mx = nm;
    }
    const float inv = 1.f / s;
    for (int m = 0; m < Nrows; m++) {
        float x = Eb[(size_t)m * ldn + n];
        Eb[(size_t)m * ldn + n] = __expf(x - mx) * inv;
    }
}

extern "C" void kernel_launch(void* const* d_in, const int* in_sizes, int n_in,
                              void* d_out, int out_size)
{
    const float* Q     = (const float*)d_in[0];
    const float* Kin   = (const float*)d_in[1];
    const float* V     = (const float*)d_in[2];
    const float* Wq    = (const float*)d_in[3];
    const float* bq    = (const float*)d_in[4];
    const float* Wk    = (const float*)d_in[5];
    const float* bk    = (const float*)d_in[6];
    const float* Wv    = (const float*)d_in[7];
    const float* bv    = (const float*)d_in[8];
    const float* gamma = (const float*)d_in[9];
    float* out = (float*)d_out;

    float *q, *kt, *v, *e;
    cudaGetSymbolAddress((void**)&q,  g_q);
    cudaGetSymbolAddress((void**)&kt, g_kt);
    cudaGetSymbolAddress((void**)&v,  g_v);
    cudaGetSymbolAddress((void**)&e,  g_e);

    const int B = B_, C = C_, CH = CH_, N = N_;
    dim3 blk(NTHREADS);

    // 1) q = Wq Q + bq : [CH x C] x [C x N] -> g_q [B][CH][N]
    sgemm_kernel<<<dim3(N / BN, CH / BM, B), blk>>>(
        Wq, Q, q, bq, nullptr, nullptr,
        CH, N, C, C, N, N,
        0, (size_t)C * N, (size_t)CH * N, 0, F_BIAS);

    // 2) k^T = (Wk K + bk)^T -> g_kt [B][N][CH]
    sgemm_kernel<<<dim3(N / BN, CH / BM, B), blk>>>(
        Wk, Kin, kt, bk, nullptr, nullptr,
        CH, N, C, C, N, CH,
        0, (size_t)C * N, (size_t)N * CH, 0, F_BIAS | F_TRANS);

    // 3) v = Wv V + bv -> g_v [B][C][N]
    sgemm_kernel<<<dim3(N / BN, C / BM, B), blk>>>(
        Wv, V, v, bv, nullptr, nullptr,
        C, N, C, C, N, N,
        0, (size_t)C * N, (size_t)C * N, 0, F_BIAS);

    // 4) eT[m][n] = sum_c kt[m][c] q[c][n]  (= energy[n][m]) -> g_e [B][N][N]
    sgemm_kernel<<<dim3(N / BN, N / BM, B), blk>>>(
        kt, q, e, nullptr, nullptr, nullptr,
        N, N, CH, CH, N, N,
        (size_t)N * CH, (size_t)CH * N, (size_t)N * N, 0, 0);

    // 5) softmax over m (rows of eT) per column n, in-place
    softmax_col_kernel<<<dim3(N / 128, B), 128>>>(e, N, N, (size_t)N * N);

    // 6) out = gamma * (v @ attn^T) + V : A=g_v [C x N(m)], B=eT [N(m) x N(n)]
    sgemm_kernel<<<dim3(N / BN, C / BM, B), blk>>>(
        v, e, out, nullptr, V, gamma,
        C, N, N, N, N, N,
        (size_t)C * N, (size_t)N * N, (size_t)C * N, (size_t)C * N, F_RES);
}

// round 6
// speedup vs baseline: 4.0188x; 4.0188x over previous
#include <cuda_runtime.h>
#include <cuda_bf16.h>
#include <cstdint>

// ---------------------------------------------------------------------------
// AttentionModule via mma.sync m16n8k16 bf16 (HMMA; tcgen05 is ptxas-gated to
// sm_103a and the harness targets plain sm_103).
// All GEMMs are D = A.B^T, A/B k-major bf16 split (hi/lo), split-3 passes:
//   hi*hi + hi*lo + lo*hi, fp32 accumulate  (rel err ~1e-5).
// Pipeline:
//   transpose+split Q,K,V: [C][N] f32 -> [N][C] bf16 hi/lo
//   split W
//   qt[n][ch] = Qt.Wq^T (+bq col)   kt = Kt.Wk^T (+bk)   v[c][n] = Wv.Vt^T (+bv row)
//   e[n][m]  = qt.kt^T  (f32 out)
//   attn = softmax_m(e) -> bf16 hi/lo
//   out[c][n] = gamma*(v.attn^T) + V
// ---------------------------------------------------------------------------

static const int B_ = 4, C_ = 512, CH_ = 256, N_ = 4096;

// ---------------- scratch ----------------
__device__ __align__(256) __nv_bfloat16 g_Qt_h[4L * 4096 * 512];
__device__ __align__(256) __nv_bfloat16 g_Qt_l[4L * 4096 * 512];
__device__ __align__(256) __nv_bfloat16 g_Kt_h[4L * 4096 * 512];
__device__ __align__(256) __nv_bfloat16 g_Kt_l[4L * 4096 * 512];
__device__ __align__(256) __nv_bfloat16 g_Vt_h[4L * 4096 * 512];
__device__ __align__(256) __nv_bfloat16 g_Vt_l[4L * 4096 * 512];
__device__ __align__(256) __nv_bfloat16 g_Wq_h[256 * 512];
__device__ __align__(256) __nv_bfloat16 g_Wq_l[256 * 512];
__device__ __align__(256) __nv_bfloat16 g_Wk_h[256 * 512];
__device__ __align__(256) __nv_bfloat16 g_Wk_l[256 * 512];
__device__ __align__(256) __nv_bfloat16 g_Wv_h[512 * 512];
__device__ __align__(256) __nv_bfloat16 g_Wv_l[512 * 512];
__device__ __align__(256) __nv_bfloat16 g_qt_h[4L * 4096 * 256];
__device__ __align__(256) __nv_bfloat16 g_qt_l[4L * 4096 * 256];
__device__ __align__(256) __nv_bfloat16 g_kt_h[4L * 4096 * 256];
__device__ __align__(256) __nv_bfloat16 g_kt_l[4L * 4096 * 256];
__device__ __align__(256) __nv_bfloat16 g_v_h [4L * 512 * 4096];
__device__ __align__(256) __nv_bfloat16 g_v_l [4L * 512 * 4096];
__device__ __align__(256) float         g_e   [4L * 4096 * 4096];
__device__ __align__(256) __nv_bfloat16 g_a_h [4L * 4096 * 4096];
__device__ __align__(256) __nv_bfloat16 g_a_l [4L * 4096 * 4096];

// ---------------- helpers ----------------
__device__ __forceinline__ uint32_t smem_to_u32(const void* p) {
    uint32_t a;
    asm("{ .reg .u64 t; cvta.to.shared.u64 t, %1; cvt.u32.u64 %0, t; }" : "=r"(a) : "l"(p));
    return a;
}
__device__ __forceinline__ void cp16(uint32_t dst, const void* src) {
    asm volatile("cp.async.cg.shared.global [%0], [%1], 16;" :: "r"(dst), "l"(src) : "memory");
}
__device__ __forceinline__ void cp_commit() { asm volatile("cp.async.commit_group;" ::: "memory"); }
__device__ __forceinline__ void cp_wait1()  { asm volatile("cp.async.wait_group 1;" ::: "memory"); }
__device__ __forceinline__ void cp_wait0()  { asm volatile("cp.async.wait_group 0;" ::: "memory"); }

__device__ __forceinline__ void ldsm4(uint32_t* r, uint32_t a) {
    asm volatile("ldmatrix.sync.aligned.m8n8.x4.shared.b16 {%0,%1,%2,%3}, [%4];"
                 : "=r"(r[0]), "=r"(r[1]), "=r"(r[2]), "=r"(r[3]) : "r"(a));
}
__device__ __forceinline__ uint32_t lds32(uint32_t a) {
    uint32_t v;
    asm volatile("ld.shared.b32 %0, [%1];" : "=r"(v) : "r"(a));
    return v;
}
__device__ __forceinline__ void mma16816(float* c, const uint32_t* a, const uint32_t* b) {
    asm volatile("mma.sync.aligned.m16n8k16.row.col.f32.bf16.bf16.f32 "
                 "{%0,%1,%2,%3}, {%4,%5,%6,%7}, {%8,%9}, {%0,%1,%2,%3};"
                 : "+f"(c[0]), "+f"(c[1]), "+f"(c[2]), "+f"(c[3])
                 : "r"(a[0]), "r"(a[1]), "r"(a[2]), "r"(a[3]), "r"(b[0]), "r"(b[1]));
}

// ---------------------------------------------------------------------------
// tgemm: D[i][j] = sum_k (Ah+Al)[i][k]*(Bh+Bl)[j][k], split-3.
// CTA tile 128x128, warp tile 64x32 (2x4 warps), K-chunk 32, double-buffered.
// smem tile rows padded to 80B (32 bf16 data + 16B pad) -> conflict-free.
// ---------------------------------------------------------------------------
#define LDR     80
#define TILE_S  (128 * LDR)       // 10240
#define STAGE_S (4 * TILE_S)      // 40960
#define TG_SMEM (2 * STAGE_S)     // 81920

enum { F_SPLIT = 1, F_BROW = 2, F_BCOL = 4, F_RES = 8 };

__global__ void __launch_bounds__(256, 2)
tgemm_kernel(const __nv_bfloat16* __restrict__ Ah, const __nv_bfloat16* __restrict__ Al,
             const __nv_bfloat16* __restrict__ Bh, const __nv_bfloat16* __restrict__ Bl,
             float* __restrict__ Cf, __nv_bfloat16* __restrict__ Chi, __nv_bfloat16* __restrict__ Clo,
             const float* __restrict__ bias, const float* __restrict__ R,
             const float* __restrict__ gammap,
             int Kd, int ldc, size_t sA, size_t sB, size_t sC, size_t sR, int flags)
{
    extern __shared__ char smem[];
    const uint32_t sm0 = smem_to_u32(smem);
    const int tid = threadIdx.x, wid = tid >> 5, lane = tid & 31;
    const int bz = blockIdx.z;
    const int m0 = blockIdx.y * 128;   // A rows / D rows
    const int n0 = blockIdx.x * 128;   // B rows / D cols

    const size_t ldkB = (size_t)Kd * 2;

    // per-thread cp.async geometry: tile t (Ah,Al,Bh,Bl), 64 threads/tile
    const int lt   = tid >> 6;          // 0..3
    const int r0   = (tid >> 2) & 15;   // row group
    const int seg  = tid & 3;           // 16B segment
    const __nv_bfloat16* gsel = (lt == 0) ? Ah : (lt == 1) ? Al : (lt == 2) ? Bh : Bl;
    gsel += (lt < 2) ? (size_t)bz * sA : (size_t)bz * sB;
    const int rows0 = (lt < 2) ? m0 : n0;
    const char* gthr = (const char*)gsel + (size_t)(rows0 + r0) * ldkB + seg * 16;
    const uint32_t dthr = sm0 + (uint32_t)lt * TILE_S + (uint32_t)r0 * LDR + (uint32_t)seg * 16;
    const size_t grow = ldkB * 16;

    const int nch = Kd >> 5;

    // mma geometry
    const int wm = wid & 1;             // m half (rows wm*64)
    const int wn = wid >> 1;            // n quarter (cols wn*32)
    const uint32_t a_off = (uint32_t)((((lane >> 3) & 1) * 8 + (lane & 7)) * LDR + ((lane >> 4) & 1) * 16);
    const uint32_t b_off = (uint32_t)((wn * 32 + (lane >> 2)) * LDR + (lane & 3) * 4);

    float acc[4][4][4];
    #pragma unroll
    for (int i = 0; i < 4; i++)
        #pragma unroll
        for (int j = 0; j < 4; j++)
            #pragma unroll
            for (int k = 0; k < 4; k++) acc[i][j][k] = 0.f;

    // preload chunk 0 into stage 0
    #pragma unroll
    for (int j = 0; j < 8; j++) cp16(dthr + j * 16 * LDR, gthr + (size_t)j * grow);
    cp_commit();

    for (int c = 0; c < nch; c++) {
        const int s = c & 1;
        if (c + 1 < nch) {
            const char* gn = gthr + (size_t)(c + 1) * 64;
            const uint32_t dn = dthr + (uint32_t)(s ^ 1) * STAGE_S;
            #pragma unroll
            for (int j = 0; j < 8; j++) cp16(dn + j * 16 * LDR, gn + (size_t)j * grow);
            cp_commit();
            cp_wait1();
        } else {
            cp_wait0();
        }
        __syncthreads();

        const uint32_t sb  = sm0 + (uint32_t)s * STAGE_S;
        const uint32_t sAh = sb, sAl = sb + TILE_S, sBh = sb + 2 * TILE_S, sBl = sb + 3 * TILE_S;

        #pragma unroll
        for (int ks = 0; ks < 2; ks++) {
            uint32_t bh[4][2], bl[4][2];
            #pragma unroll
            for (int nt = 0; nt < 4; nt++) {
                const uint32_t bo = b_off + (uint32_t)(nt * 8 * LDR + ks * 32);
                bh[nt][0] = lds32(sBh + bo);
                bh[nt][1] = lds32(sBh + bo + 16);
                bl[nt][0] = lds32(sBl + bo);
                bl[nt][1] = lds32(sBl + bo + 16);
            }
            uint32_t af[4][4];
            #pragma unroll
            for (int mt = 0; mt < 4; mt++)
                ldsm4(af[mt], sAh + (uint32_t)((wm * 64 + mt * 16) * LDR + ks * 32) + a_off);
            #pragma unroll
            for (int mt = 0; mt < 4; mt++)
                #pragma unroll
                for (int nt = 0; nt < 4; nt++) mma16816(acc[mt][nt], af[mt], bh[nt]);
            #pragma unroll
            for (int mt = 0; mt < 4; mt++)
                #pragma unroll
                for (int nt = 0; nt < 4; nt++) mma16816(acc[mt][nt], af[mt], bl[nt]);
            #pragma unroll
            for (int mt = 0; mt < 4; mt++)
                ldsm4(af[mt], sAl + (uint32_t)((wm * 64 + mt * 16) * LDR + ks * 32) + a_off);
            #pragma unroll
            for (int mt = 0; mt < 4; mt++)
                #pragma unroll
                for (int nt = 0; nt < 4; nt++) mma16816(acc[mt][nt], af[mt], bh[nt]);
        }
        __syncthreads();
    }

    // ---------------- epilogue ----------------
    const float g = (flags & F_RES) ? *gammap : 0.f;
    const int r4 = lane >> 2, c2 = (lane & 3) * 2;

    #pragma unroll
    for (int mt = 0; mt < 4; mt++) {
        #pragma unroll
        for (int h = 0; h < 2; h++) {
            const int row = m0 + wm * 64 + mt * 16 + r4 + h * 8;
            const float br = (flags & F_BROW) ? bias[row] : 0.f;
            #pragma unroll
            for (int nt = 0; nt < 4; nt++) {
                const int col = n0 + wn * 32 + nt * 8 + c2;
                float v0 = acc[mt][nt][h * 2 + 0];
                float v1 = acc[mt][nt][h * 2 + 1];
                if (flags & F_BCOL) { v0 += bias[col]; v1 += bias[col + 1]; }
                else                { v0 += br;        v1 += br; }
                const size_t idx = (size_t)row * ldc + col;
                if (flags & F_SPLIT) {
                    __nv_bfloat16 h0 = __float2bfloat16_rn(v0);
                    __nv_bfloat16 h1 = __float2bfloat16_rn(v1);
                    __nv_bfloat16 l0 = __float2bfloat16_rn(v0 - __bfloat162float(h0));
                    __nv_bfloat16 l1 = __float2bfloat16_rn(v1 - __bfloat162float(h1));
                    uint32_t hp, lp;
                    hp = (uint32_t)__bfloat16_as_ushort(h0) | ((uint32_t)__bfloat16_as_ushort(h1) << 16);
                    lp = (uint32_t)__bfloat16_as_ushort(l0) | ((uint32_t)__bfloat16_as_ushort(l1) << 16);
                    *(uint32_t*)(Chi + (size_t)bz * sC + idx) = hp;
                    *(uint32_t*)(Clo + (size_t)bz * sC + idx) = lp;
                } else if (flags & F_RES) {
                    const float2 rv = *(const float2*)(R + (size_t)bz * sR + idx);
                    float2 o;
                    o.x = g * v0 + rv.x;
                    o.y = g * v1 + rv.y;
                    *(float2*)(Cf + (size_t)bz * sC + idx) = o;
                } else {
                    float2 o;
                    o.x = v0;
                    o.y = v1;
                    *(float2*)(Cf + (size_t)bz * sC + idx) = o;
                }
            }
        }
    }
}

// ---------------------------------------------------------------------------
// transpose + split: X [rows][cols] f32 -> T hi/lo [cols][rows] bf16
// ---------------------------------------------------------------------------
__global__ __launch_bounds__(256)
void transpose_split(const float* __restrict__ X,
                     __nv_bfloat16* __restrict__ Th, __nv_bfloat16* __restrict__ Tl,
                     int rows, int cols)
{
    __shared__ float t[32][33];
    const int bz = blockIdx.z;
    const size_t bo = (size_t)bz * rows * cols;
    X += bo; Th += bo; Tl += bo;
    const int x0 = blockIdx.x * 32;   // col in X
    const int y0 = blockIdx.y * 32;   // row in X
    const int tx = threadIdx.x & 31, ty = threadIdx.x >> 5;  // 32 x 8

    #pragma unroll
    for (int j = 0; j < 32; j += 8)
        t[ty + j][tx] = X[(size_t)(y0 + ty + j) * cols + x0 + tx];
    __syncthreads();
    #pragma unroll
    for (int j = 0; j < 32; j += 8) {
        const float v = t[tx][ty + j];
        const __nv_bfloat16 h = __float2bfloat16_rn(v);
        const __nv_bfloat16 l = __float2bfloat16_rn(v - __bfloat162float(h));
        const size_t idx = (size_t)(x0 + ty + j) * rows + y0 + tx;
        Th[idx] = h;
        Tl[idx] = l;
    }
}

__global__ void split_w(const float* __restrict__ W,
                        __nv_bfloat16* __restrict__ H, __nv_bfloat16* __restrict__ L, int n)
{
    const int i = blockIdx.x * blockDim.x + threadIdx.x;
    if (i < n) {
        const float v = W[i];
        const __nv_bfloat16 h = __float2bfloat16_rn(v);
        H[i] = h;
        L[i] = __float2bfloat16_rn(v - __bfloat162float(h));
    }
}

// ---------------------------------------------------------------------------
// row softmax over e [.][4096], whole row in regs, poly exp2; writes bf16 hi/lo
// ---------------------------------------------------------------------------
__device__ __forceinline__ float fexp(float x) {  // exp(x), x <= 0
    float t = fmaxf(x * 1.44269504f, -126.f);
    float fi = floorf(t);
    float f = t - fi;
    float p = 1.5465324e-4f;
    p = p * f + 1.3333558e-3f;
    p = p * f + 9.6181291e-3f;
    p = p * f + 5.5504109e-2f;
    p = p * f + 2.4022651e-1f;
    p = p * f + 6.9314718e-1f;
    p = p * f + 1.0f;
    return p * __int_as_float(((int)fi + 127) << 23);
}

__global__ __launch_bounds__(256)
void softmax_row(const float* __restrict__ E,
                 __nv_bfloat16* __restrict__ Ah, __nv_bfloat16* __restrict__ Al, int Ncols)
{
    const int row = blockIdx.x;
    const int bz = blockIdx.y;
    const size_t base = ((size_t)bz * gridDim.x + row) * Ncols;
    const int tid = threadIdx.x, wid = tid >> 5, lid = tid & 31;

    __shared__ float sbuf[8];

    float x[16];
    const float4* rp = (const float4*)(E + base);
    #pragma unroll
    for (int k = 0; k < 4; k++) {
        float4 v4 = rp[tid + k * 256];
        x[k * 4 + 0] = v4.x; x[k * 4 + 1] = v4.y; x[k * 4 + 2] = v4.z; x[k * 4 + 3] = v4.w;
    }

    float m = x[0];
    #pragma unroll
    for (int i = 1; i < 16; i++) m = fmaxf(m, x[i]);
    #pragma unroll
    for (int o = 16; o; o >>= 1) m = fmaxf(m, __shfl_xor_sync(0xffffffffu, m, o));
    if (lid == 0) sbuf[wid] = m;
    __syncthreads();
    float mx = sbuf[0];
    #pragma unroll
    for (int i = 1; i < 8; i++) mx = fmaxf(mx, sbuf[i]);
    __syncthreads();

    float s = 0.f;
    #pragma unroll
    for (int i = 0; i < 16; i++) { x[i] = fexp(x[i] - mx); s += x[i]; }
    #pragma unroll
    for (int o = 16; o; o >>= 1) s += __shfl_xor_sync(0xffffffffu, s, o);
    if (lid == 0) sbuf[wid] = s;
    __syncthreads();
    float tot = 0.f;
    #pragma unroll
    for (int i = 0; i < 8; i++) tot += sbuf[i];
    const float inv = 1.f / tot;

    #pragma unroll
    for (int k = 0; k < 4; k++) {
        uint32_t hp[2], lp[2];
        #pragma unroll
        for (int j = 0; j < 4; j++) {
            const float y = x[k * 4 + j] * inv;
            const __nv_bfloat16 h = __float2bfloat16_rn(y);
            const __nv_bfloat16 l = __float2bfloat16_rn(y - __bfloat162float(h));
            ((unsigned short*)hp)[j] = __bfloat16_as_ushort(h);
            ((unsigned short*)lp)[j] = __bfloat16_as_ushort(l);
        }
        const size_t idx = base + (size_t)(tid + k * 256) * 4;
        *(uint2*)(Ah + idx) = *(const uint2*)hp;
        *(uint2*)(Al + idx) = *(const uint2*)lp;
    }
}

// ---------------------------------------------------------------------------
extern "C" void kernel_launch(void* const* d_in, const int* in_sizes, int n_in,
                              void* d_out, int out_size)
{
    const float* Q     = (const float*)d_in[0];
    const float* Kin   = (const float*)d_in[1];
    const float* V     = (const float*)d_in[2];
    const float* Wq    = (const float*)d_in[3];
    const float* bq    = (const float*)d_in[4];
    const float* Wk    = (const float*)d_in[5];
    const float* bk    = (const float*)d_in[6];
    const float* Wv    = (const float*)d_in[7];
    const float* bv    = (const float*)d_in[8];
    const float* gamma = (const float*)d_in[9];
    float* out = (float*)d_out;

    __nv_bfloat16 *Qt_h, *Qt_l, *Kt_h, *Kt_l, *Vt_h, *Vt_l;
    __nv_bfloat16 *Wq_h, *Wq_l, *Wk_h, *Wk_l, *Wv_h, *Wv_l;
    __nv_bfloat16 *qt_h, *qt_l, *kt_h, *kt_l, *v_h, *v_l, *a_h, *a_l;
    float* e;
    cudaGetSymbolAddress((void**)&Qt_h, g_Qt_h); cudaGetSymbolAddress((void**)&Qt_l, g_Qt_l);
    cudaGetSymbolAddress((void**)&Kt_h, g_Kt_h); cudaGetSymbolAddress((void**)&Kt_l, g_Kt_l);
    cudaGetSymbolAddress((void**)&Vt_h, g_Vt_h); cudaGetSymbolAddress((void**)&Vt_l, g_Vt_l);
    cudaGetSymbolAddress((void**)&Wq_h, g_Wq_h); cudaGetSymbolAddress((void**)&Wq_l, g_Wq_l);
    cudaGetSymbolAddress((void**)&Wk_h, g_Wk_h); cudaGetSymbolAddress((void**)&Wk_l, g_Wk_l);
    cudaGetSymbolAddress((void**)&Wv_h, g_Wv_h); cudaGetSymbolAddress((void**)&Wv_l, g_Wv_l);
    cudaGetSymbolAddress((void**)&qt_h, g_qt_h); cudaGetSymbolAddress((void**)&qt_l, g_qt_l);
    cudaGetSymbolAddress((void**)&kt_h, g_kt_h); cudaGetSymbolAddress((void**)&kt_l, g_kt_l);
    cudaGetSymbolAddress((void**)&v_h,  g_v_h);  cudaGetSymbolAddress((void**)&v_l,  g_v_l);
    cudaGetSymbolAddress((void**)&a_h,  g_a_h);  cudaGetSymbolAddress((void**)&a_l,  g_a_l);
    cudaGetSymbolAddress((void**)&e,    g_e);

    const int B = B_, C = C_, CH = CH_, N = N_;

    cudaFuncSetAttribute(tgemm_kernel, cudaFuncAttributeMaxDynamicSharedMemorySize, TG_SMEM);

    // weight splits
    split_w<<<(CH * C + 255) / 256, 256>>>(Wq, Wq_h, Wq_l, CH * C);
    split_w<<<(CH * C + 255) / 256, 256>>>(Wk, Wk_h, Wk_l, CH * C);
    split_w<<<(C * C + 255) / 256, 256>>>(Wv, Wv_h, Wv_l, C * C);

    // input transpose+split: [C][N] -> [N][C] hi/lo
    dim3 tgrid(N / 32, C / 32, B);
    transpose_split<<<tgrid, 256>>>(Q,   Qt_h, Qt_l, C, N);
    transpose_split<<<tgrid, 256>>>(Kin, Kt_h, Kt_l, C, N);
    transpose_split<<<tgrid, 256>>>(V,   Vt_h, Vt_l, C, N);

    // qt[n][ch] = Qt . Wq^T + bq[ch]   (split out, col bias)
    tgemm_kernel<<<dim3(CH / 128, N / 128, B), 256, TG_SMEM>>>(
        Qt_h, Qt_l, Wq_h, Wq_l, nullptr, qt_h, qt_l, bq, nullptr, nullptr,
        C, CH, (size_t)N * C, 0, (size_t)N * CH, 0, F_SPLIT | F_BCOL);
    // kt[n][ch]
    tgemm_kernel<<<dim3(CH / 128, N / 128, B), 256, TG_SMEM>>>(
        Kt_h, Kt_l, Wk_h, Wk_l, nullptr, kt_h, kt_l, bk, nullptr, nullptr,
        C, CH, (size_t)N * C, 0, (size_t)N * CH, 0, F_SPLIT | F_BCOL);
    // v[c][n] = Wv . Vt^T + bv[c]  (A unbatched)
    tgemm_kernel<<<dim3(N / 128, C / 128, B), 256, TG_SMEM>>>(
        Wv_h, Wv_l, Vt_h, Vt_l, nullptr, v_h, v_l, bv, nullptr, nullptr,
        C, N, 0, (size_t)N * C, (size_t)C * N, 0, F_SPLIT | F_BROW);

    // e[n][m] = qt . kt^T  (f32 out)
    tgemm_kernel<<<dim3(N / 128, N / 128, B), 256, TG_SMEM>>>(
        qt_h, qt_l, kt_h, kt_l, e, nullptr, nullptr, nullptr, nullptr, nullptr,
        CH, N, (size_t)N * CH, (size_t)N * CH, (size_t)N * N, 0, 0);

    // attention = softmax_m(e) -> bf16 hi/lo
    softmax_row<<<dim3(N, B), 256>>>(e, a_h, a_l, N);

    // out[c][n] = gamma * (v . attn^T) + V
    tgemm_kernel<<<dim3(N / 128, C / 128, B), 256, TG_SMEM>>>(
        v_h, v_l, a_h, a_l, out, nullptr, nullptr, nullptr, V, gamma,
        N, N, (size_t)C * N, (size_t)N * N, (size_t)C * N, (size_t)C * N, F_RES);
}

// round 7
// speedup vs baseline: 4.0369x; 1.0045x over previous
#include <cuda_runtime.h>
#include <cuda_bf16.h>
#include <cstdint>

// ---------------------------------------------------------------------------
// AttentionModule via mma.sync m16n8k16 bf16 (HMMA; tcgen05 is ptxas-gated to
// sm_103a and the harness targets plain sm_103).
// All GEMMs are D = A.B^T, A/B k-major bf16 split (hi/lo), split-3 passes:
//   hi*hi + hi*lo + lo*hi, fp32 accumulate  (rel err ~1e-5).
// Round 7: CTA tile 128x256, warp tile 64x64, ldmatrix for A and B.
//   smem bytes/MAC drops from ~125 B/cyc-equivalent (at crossbar limit) to ~84.
// ---------------------------------------------------------------------------

static const int B_ = 4, C_ = 512, CH_ = 256, N_ = 4096;

// ---------------- scratch ----------------
__device__ __align__(256) __nv_bfloat16 g_Qt_h[4L * 4096 * 512];
__device__ __align__(256) __nv_bfloat16 g_Qt_l[4L * 4096 * 512];
__device__ __align__(256) __nv_bfloat16 g_Kt_h[4L * 4096 * 512];
__device__ __align__(256) __nv_bfloat16 g_Kt_l[4L * 4096 * 512];
__device__ __align__(256) __nv_bfloat16 g_Vt_h[4L * 4096 * 512];
__device__ __align__(256) __nv_bfloat16 g_Vt_l[4L * 4096 * 512];
__device__ __align__(256) __nv_bfloat16 g_Wq_h[256 * 512];
__device__ __align__(256) __nv_bfloat16 g_Wq_l[256 * 512];
__device__ __align__(256) __nv_bfloat16 g_Wk_h[256 * 512];
__device__ __align__(256) __nv_bfloat16 g_Wk_l[256 * 512];
__device__ __align__(256) __nv_bfloat16 g_Wv_h[512 * 512];
__device__ __align__(256) __nv_bfloat16 g_Wv_l[512 * 512];
__device__ __align__(256) __nv_bfloat16 g_qt_h[4L * 4096 * 256];
__device__ __align__(256) __nv_bfloat16 g_qt_l[4L * 4096 * 256];
__device__ __align__(256) __nv_bfloat16 g_kt_h[4L * 4096 * 256];
__device__ __align__(256) __nv_bfloat16 g_kt_l[4L * 4096 * 256];
__device__ __align__(256) __nv_bfloat16 g_v_h [4L * 512 * 4096];
__device__ __align__(256) __nv_bfloat16 g_v_l [4L * 512 * 4096];
__device__ __align__(256) float         g_e   [4L * 4096 * 4096];
__device__ __align__(256) __nv_bfloat16 g_a_h [4L * 4096 * 4096];
__device__ __align__(256) __nv_bfloat16 g_a_l [4L * 4096 * 4096];

// ---------------- helpers ----------------
__device__ __forceinline__ uint32_t smem_to_u32(const void* p) {
    uint32_t a;
    asm("{ .reg .u64 t; cvta.to.shared.u64 t, %1; cvt.u32.u64 %0, t; }" : "=r"(a) : "l"(p));
    return a;
}
__device__ __forceinline__ void cp16(uint32_t dst, const void* src) {
    asm volatile("cp.async.cg.shared.global [%0], [%1], 16;" :: "r"(dst), "l"(src) : "memory");
}
__device__ __forceinline__ void cp_commit() { asm volatile("cp.async.commit_group;" ::: "memory"); }
__device__ __forceinline__ void cp_wait1()  { asm volatile("cp.async.wait_group 1;" ::: "memory"); }
__device__ __forceinline__ void cp_wait0()  { asm volatile("cp.async.wait_group 0;" ::: "memory"); }

__device__ __forceinline__ void ldsm4(uint32_t* r, uint32_t a) {
    asm volatile("ldmatrix.sync.aligned.m8n8.x4.shared.b16 {%0,%1,%2,%3}, [%4];"
                 : "=r"(r[0]), "=r"(r[1]), "=r"(r[2]), "=r"(r[3]) : "r"(a));
}
__device__ __forceinline__ void mma16816(float* c, const uint32_t* a, const uint32_t* b) {
    asm volatile("mma.sync.aligned.m16n8k16.row.col.f32.bf16.bf16.f32 "
                 "{%0,%1,%2,%3}, {%4,%5,%6,%7}, {%8,%9}, {%0,%1,%2,%3};"
                 : "+f"(c[0]), "+f"(c[1]), "+f"(c[2]), "+f"(c[3])
                 : "r"(a[0]), "r"(a[1]), "r"(a[2]), "r"(a[3]), "r"(b[0]), "r"(b[1]));
}

// ---------------------------------------------------------------------------
// tgemm: D[i][j] = sum_k (Ah+Al)[i][k]*(Bh+Bl)[j][k], split-3.
// CTA tile 128x256, warp tile 64x64 (warps 2 x 4), K-chunk 32, double buffer.
// smem rows padded to 80B -> conflict-free ldmatrix for A and B.
// ---------------------------------------------------------------------------
#define LDR     80
#define A_TILE  (128 * LDR)                 // 10240
#define B_TILE  (256 * LDR)                 // 20480
#define STAGE_S (2 * A_TILE + 2 * B_TILE)   // 61440
#define TG_SMEM (2 * STAGE_S)               // 122880

enum { F_SPLIT = 1, F_BROW = 2, F_BCOL = 4, F_RES = 8 };

__global__ void __launch_bounds__(256, 1)
tgemm_kernel(const __nv_bfloat16* __restrict__ Ah, const __nv_bfloat16* __restrict__ Al,
             const __nv_bfloat16* __restrict__ Bh, const __nv_bfloat16* __restrict__ Bl,
             float* __restrict__ Cf, __nv_bfloat16* __restrict__ Chi, __nv_bfloat16* __restrict__ Clo,
             const float* __restrict__ bias, const float* __restrict__ R,
             const float* __restrict__ gammap,
             int Kd, int ldc, size_t sA, size_t sB, size_t sC, size_t sR, int flags)
{
    extern __shared__ char smem[];
    const uint32_t sm0 = smem_to_u32(smem);
    const int tid = threadIdx.x, wid = tid >> 5, lane = tid & 31;
    const int bz = blockIdx.z;
    const int m0 = blockIdx.y * 128;   // A rows / D rows
    const int n0 = blockIdx.x * 256;   // B rows / D cols

    const size_t ldkB = (size_t)Kd * 2;

    // cp.async geometry: 256 threads x 12 x 16B = 48KB/chunk.
    // thread owns row base lr (0..63), 16B segment seg (0..3); row j*64 strides.
    const int lr = tid >> 2, seg = tid & 3;
    const char* gA_h = (const char*)(Ah + (size_t)bz * sA) + (size_t)(m0 + lr) * ldkB + seg * 16;
    const char* gA_l = (const char*)(Al + (size_t)bz * sA) + (size_t)(m0 + lr) * ldkB + seg * 16;
    const char* gB_h = (const char*)(Bh + (size_t)bz * sB) + (size_t)(n0 + lr) * ldkB + seg * 16;
    const char* gB_l = (const char*)(Bl + (size_t)bz * sB) + (size_t)(n0 + lr) * ldkB + seg * 16;
    const size_t g64 = 64 * ldkB;
    const uint32_t dthr = sm0 + (uint32_t)lr * LDR + (uint32_t)seg * 16;

    const int nch = Kd >> 5;

    // mma geometry: warp (wm, wn) covers rows wm*64.., cols wn*64..
    const int wm = wid & 1, wn = wid >> 2 == 0 ? (wid >> 1) : (wid >> 1);  // wn = wid>>1
    const int wncol = (wid >> 1) * 64;
    const uint32_t a_off = (uint32_t)((lane & 15) * LDR + (lane >> 4) * 16);
    const uint32_t b_off = (uint32_t)(((lane & 7) + ((lane >> 4) & 1) * 8) * LDR + ((lane >> 3) & 1) * 16);
    (void)wn;

    float acc[4][8][4];
    #pragma unroll
    for (int i = 0; i < 4; i++)
        #pragma unroll
        for (int j = 0; j < 8; j++)
            #pragma unroll
            for (int k = 0; k < 4; k++) acc[i][j][k] = 0.f;

#define TG_LOAD(s, c) do { \
        const size_t _ko = (size_t)(c) * 64; \
        const uint32_t _d = dthr + (uint32_t)(s) * STAGE_S; \
        cp16(_d,                     gA_h + _ko); \
        cp16(_d + 64 * LDR,          gA_h + _ko + g64); \
        cp16(_d + A_TILE,            gA_l + _ko); \
        cp16(_d + A_TILE + 64 * LDR, gA_l + _ko + g64); \
        _Pragma("unroll") \
        for (int _j = 0; _j < 4; _j++) \
            cp16(_d + 2 * A_TILE + _j * 64 * LDR, gB_h + _ko + _j * g64); \
        _Pragma("unroll") \
        for (int _j = 0; _j < 4; _j++) \
            cp16(_d + 2 * A_TILE + B_TILE + _j * 64 * LDR, gB_l + _ko + _j * g64); \
        cp_commit(); \
    } while (0)

    TG_LOAD(0, 0);

    for (int c = 0; c < nch; c++) {
        const int s = c & 1;
        if (c + 1 < nch) {
            TG_LOAD(s ^ 1, c + 1);
            cp_wait1();
        } else {
            cp_wait0();
        }
        __syncthreads();

        const uint32_t sb  = sm0 + (uint32_t)s * STAGE_S;
        const uint32_t sAh = sb, sAl = sb + A_TILE;
        const uint32_t sBh = sb + 2 * A_TILE, sBl = sBh + B_TILE;

        #pragma unroll
        for (int ks = 0; ks < 2; ks++) {
            const uint32_t ko = ks * 32;
            uint32_t bh[8][2], bl[8][2], af[4][4];
            #pragma unroll
            for (int p = 0; p < 4; p++) {
                uint32_t r[4];
                ldsm4(r, sBh + (uint32_t)(wncol + p * 16) * LDR + ko + b_off);
                bh[2 * p][0] = r[0]; bh[2 * p][1] = r[1];
                bh[2 * p + 1][0] = r[2]; bh[2 * p + 1][1] = r[3];
            }
            #pragma unroll
            for (int mt = 0; mt < 4; mt++)
                ldsm4(af[mt], sAh + (uint32_t)(wm * 64 + mt * 16) * LDR + ko + a_off);
            #pragma unroll
            for (int mt = 0; mt < 4; mt++)
                #pragma unroll
                for (int nt = 0; nt < 8; nt++) mma16816(acc[mt][nt], af[mt], bh[nt]);
            #pragma unroll
            for (int p = 0; p < 4; p++) {
                uint32_t r[4];
                ldsm4(r, sBl + (uint32_t)(wncol + p * 16) * LDR + ko + b_off);
                bl[2 * p][0] = r[0]; bl[2 * p][1] = r[1];
                bl[2 * p + 1][0] = r[2]; bl[2 * p + 1][1] = r[3];
            }
            #pragma unroll
            for (int mt = 0; mt < 4; mt++)
                #pragma unroll
                for (int nt = 0; nt < 8; nt++) mma16816(acc[mt][nt], af[mt], bl[nt]);
            #pragma unroll
            for (int mt = 0; mt < 4; mt++)
                ldsm4(af[mt], sAl + (uint32_t)(wm * 64 + mt * 16) * LDR + ko + a_off);
            #pragma unroll
            for (int mt = 0; mt < 4; mt++)
                #pragma unroll
                for (int nt = 0; nt < 8; nt++) mma16816(acc[mt][nt], af[mt], bh[nt]);
        }
        __syncthreads();
    }

    // ---------------- epilogue ----------------
    const float g = (flags & F_RES) ? *gammap : 0.f;

    #pragma unroll
    for (int mt = 0; mt < 4; mt++) {
        #pragma unroll
        for (int h = 0; h < 2; h++) {
            const int row = m0 + wm * 64 + mt * 16 + (lane >> 2) + h * 8;
            const float br = (flags & F_BROW) ? bias[row] : 0.f;
            #pragma unroll
            for (int nt = 0; nt < 8; nt++) {
                const int col = n0 + wncol + nt * 8 + (lane & 3) * 2;
                float v0 = acc[mt][nt][h * 2 + 0];
                float v1 = acc[mt][nt][h * 2 + 1];
                if (flags & F_BCOL) { v0 += bias[col]; v1 += bias[col + 1]; }
                else                { v0 += br;        v1 += br; }
                const size_t idx = (size_t)row * ldc + col;
                if (flags & F_SPLIT) {
                    __nv_bfloat16 h0 = __float2bfloat16_rn(v0);
                    __nv_bfloat16 h1 = __float2bfloat16_rn(v1);
                    __nv_bfloat16 l0 = __float2bfloat16_rn(v0 - __bfloat162float(h0));
                    __nv_bfloat16 l1 = __float2bfloat16_rn(v1 - __bfloat162float(h1));
                    uint32_t hp, lp;
                    hp = (uint32_t)__bfloat16_as_ushort(h0) | ((uint32_t)__bfloat16_as_ushort(h1) << 16);
                    lp = (uint32_t)__bfloat16_as_ushort(l0) | ((uint32_t)__bfloat16_as_ushort(l1) << 16);
                    *(uint32_t*)(Chi + (size_t)bz * sC + idx) = hp;
                    *(uint32_t*)(Clo + (size_t)bz * sC + idx) = lp;
                } else if (flags & F_RES) {
                    const float2 rv = *(const float2*)(R + (size_t)bz * sR + idx);
                    float2 o;
                    o.x = g * v0 + rv.x;
                    o.y = g * v1 + rv.y;
                    *(float2*)(Cf + (size_t)bz * sC + idx) = o;
                } else {
                    float2 o;
                    o.x = v0;
                    o.y = v1;
                    *(float2*)(Cf + (size_t)bz * sC + idx) = o;
                }
            }
        }
    }
}

// ---------------------------------------------------------------------------
// transpose + split: X [rows][cols] f32 -> T hi/lo [cols][rows] bf16
// ---------------------------------------------------------------------------
__global__ __launch_bounds__(256)
void transpose_split(const float* __restrict__ X,
                     __nv_bfloat16* __restrict__ Th, __nv_bfloat16* __restrict__ Tl,
                     int rows, int cols)
{
    __shared__ float t[32][33];
    const int bz = blockIdx.z;
    const size_t bo = (size_t)bz * rows * cols;
    X += bo; Th += bo; Tl += bo;
    const int x0 = blockIdx.x * 32;
    const int y0 = blockIdx.y * 32;
    const int tx = threadIdx.x & 31, ty = threadIdx.x >> 5;

    #pragma unroll
    for (int j = 0; j < 32; j += 8)
        t[ty + j][tx] = X[(size_t)(y0 + ty + j) * cols + x0 + tx];
    __syncthreads();
    #pragma unroll
    for (int j = 0; j < 32; j += 8) {
        const float v = t[tx][ty + j];
        const __nv_bfloat16 h = __float2bfloat16_rn(v);
        const __nv_bfloat16 l = __float2bfloat16_rn(v - __bfloat162float(h));
        const size_t idx = (size_t)(x0 + ty + j) * rows + y0 + tx;
        Th[idx] = h;
        Tl[idx] = l;
    }
}

__global__ void split_w(const float* __restrict__ W,
                        __nv_bfloat16* __restrict__ H, __nv_bfloat16* __restrict__ L, int n)
{
    const int i = blockIdx.x * blockDim.x + threadIdx.x;
    if (i < n) {
        const float v = W[i];
        const __nv_bfloat16 h = __float2bfloat16_rn(v);
        H[i] = h;
        L[i] = __float2bfloat16_rn(v - __bfloat162float(h));
    }
}

// ---------------------------------------------------------------------------
// row softmax over e [.][4096], whole row in regs, poly exp2; bf16 hi/lo out
// ---------------------------------------------------------------------------
__device__ __forceinline__ float fexp(float x) {  // exp(x), x <= 0
    float t = fmaxf(x * 1.44269504f, -126.f);
    float fi = floorf(t);
    float f = t - fi;
    float p = 1.5465324e-4f;
    p = p * f + 1.3333558e-3f;
    p = p * f + 9.6181291e-3f;
    p = p * f + 5.5504109e-2f;
    p = p * f + 2.4022651e-1f;
    p = p * f + 6.9314718e-1f;
    p = p * f + 1.0f;
    return p * __int_as_float(((int)fi + 127) << 23);
}

__global__ __launch_bounds__(256)
void softmax_row(const float* __restrict__ E,
                 __nv_bfloat16* __restrict__ Ah, __nv_bfloat16* __restrict__ Al, int Ncols)
{
    const int row = blockIdx.x;
    const int bz = blockIdx.y;
    const size_t base = ((size_t)bz * gridDim.x + row) * Ncols;
    const int tid = threadIdx.x, wid = tid >> 5, lid = tid & 31;

    __shared__ float sbuf[8];

    float x[16];
    const float4* rp = (const float4*)(E + base);
    #pragma unroll
    for (int k = 0; k < 4; k++) {
        float4 v4 = rp[tid + k * 256];
        x[k * 4 + 0] = v4.x; x[k * 4 + 1] = v4.y; x[k * 4 + 2] = v4.z; x[k * 4 + 3] = v4.w;
    }

    float m = x[0];
    #pragma unroll
    for (int i = 1; i < 16; i++) m = fmaxf(m, x[i]);
    #pragma unroll
    for (int o = 16; o; o >>= 1) m = fmaxf(m, __shfl_xor_sync(0xffffffffu, m, o));
    if (lid == 0) sbuf[wid] = m;
    __syncthreads();
    float mx = sbuf[0];
    #pragma unroll
    for (int i = 1; i < 8; i++) mx = fmaxf(mx, sbuf[i]);
    __syncthreads();

    float s = 0.f;
    #pragma unroll
    for (int i = 0; i < 16; i++) { x[i] = fexp(x[i] - mx); s += x[i]; }
    #pragma unroll
    for (int o = 16; o; o >>= 1) s += __shfl_xor_sync(0xffffffffu, s, o);
    if (lid == 0) sbuf[wid] = s;
    __syncthreads();
    float tot = 0.f;
    #pragma unroll
    for (int i = 0; i < 8; i++) tot += sbuf[i];
    const float inv = 1.f / tot;

    #pragma unroll
    for (int k = 0; k < 4; k++) {
        uint32_t hp[2], lp[2];
        #pragma unroll
        for (int j = 0; j < 4; j++) {
            const float y = x[k * 4 + j] * inv;
            const __nv_bfloat16 h = __float2bfloat16_rn(y);
            const __nv_bfloat16 l = __float2bfloat16_rn(y - __bfloat162float(h));
            ((unsigned short*)hp)[j] = __bfloat16_as_ushort(h);
            ((unsigned short*)lp)[j] = __bfloat16_as_ushort(l);
        }
        const size_t idx = base + (size_t)(tid + k * 256) * 4;
        *(uint2*)(Ah + idx) = *(const uint2*)hp;
        *(uint2*)(Al + idx) = *(const uint2*)lp;
    }
}

// ---------------------------------------------------------------------------
extern "C" void kernel_launch(void* const* d_in, const int* in_sizes, int n_in,
                              void* d_out, int out_size)
{
    const float* Q     = (const float*)d_in[0];
    const float* Kin   = (const float*)d_in[1];
    const float* V     = (const float*)d_in[2];
    const float* Wq    = (const float*)d_in[3];
    const float* bq    = (const float*)d_in[4];
    const float* Wk    = (const float*)d_in[5];
    const float* bk    = (const float*)d_in[6];
    const float* Wv    = (const float*)d_in[7];
    const float* bv    = (const float*)d_in[8];
    const float* gamma = (const float*)d_in[9];
    float* out = (float*)d_out;

    __nv_bfloat16 *Qt_h, *Qt_l, *Kt_h, *Kt_l, *Vt_h, *Vt_l;
    __nv_bfloat16 *Wq_h, *Wq_l, *Wk_h, *Wk_l, *Wv_h, *Wv_l;
    __nv_bfloat16 *qt_h, *qt_l, *kt_h, *kt_l, *v_h, *v_l, *a_h, *a_l;
    float* e;
    cudaGetSymbolAddress((void**)&Qt_h, g_Qt_h); cudaGetSymbolAddress((void**)&Qt_l, g_Qt_l);
    cudaGetSymbolAddress((void**)&Kt_h, g_Kt_h); cudaGetSymbolAddress((void**)&Kt_l, g_Kt_l);
    cudaGetSymbolAddress((void**)&Vt_h, g_Vt_h); cudaGetSymbolAddress((void**)&Vt_l, g_Vt_l);
    cudaGetSymbolAddress((void**)&Wq_h, g_Wq_h); cudaGetSymbolAddress((void**)&Wq_l, g_Wq_l);
    cudaGetSymbolAddress((void**)&Wk_h, g_Wk_h); cudaGetSymbolAddress((void**)&Wk_l, g_Wk_l);
    cudaGetSymbolAddress((void**)&Wv_h, g_Wv_h); cudaGetSymbolAddress((void**)&Wv_l, g_Wv_l);
    cudaGetSymbolAddress((void**)&qt_h, g_qt_h); cudaGetSymbolAddress((void**)&qt_l, g_qt_l);
    cudaGetSymbolAddress((void**)&kt_h, g_kt_h); cudaGetSymbolAddress((void**)&kt_l, g_kt_l);
    cudaGetSymbolAddress((void**)&v_h,  g_v_h);  cudaGetSymbolAddress((void**)&v_l,  g_v_l);
    cudaGetSymbolAddress((void**)&a_h,  g_a_h);  cudaGetSymbolAddress((void**)&a_l,  g_a_l);
    cudaGetSymbolAddress((void**)&e,    g_e);

    const int B = B_, C = C_, CH = CH_, N = N_;

    cudaFuncSetAttribute(tgemm_kernel, cudaFuncAttributeMaxDynamicSharedMemorySize, TG_SMEM);

    // weight splits
    split_w<<<(CH * C + 255) / 256, 256>>>(Wq, Wq_h, Wq_l, CH * C);
    split_w<<<(CH * C + 255) / 256, 256>>>(Wk, Wk_h, Wk_l, CH * C);
    split_w<<<(C * C + 255) / 256, 256>>>(Wv, Wv_h, Wv_l, C * C);

    // input transpose+split: [C][N] -> [N][C] hi/lo
    dim3 tgrid(N / 32, C / 32, B);
    transpose_split<<<tgrid, 256>>>(Q,   Qt_h, Qt_l, C, N);
    transpose_split<<<tgrid, 256>>>(Kin, Kt_h, Kt_l, C, N);
    transpose_split<<<tgrid, 256>>>(V,   Vt_h, Vt_l, C, N);

    // qt[n][ch] = Qt . Wq^T + bq[ch]   (split out, col bias)
    tgemm_kernel<<<dim3(CH / 256, N / 128, B), 256, TG_SMEM>>>(
        Qt_h, Qt_l, Wq_h, Wq_l, nullptr, qt_h, qt_l, bq, nullptr, nullptr,
        C, CH, (size_t)N * C, 0, (size_t)N * CH, 0, F_SPLIT | F_BCOL);
    // kt[n][ch]
    tgemm_kernel<<<dim3(CH / 256, N / 128, B), 256, TG_SMEM>>>(
        Kt_h, Kt_l, Wk_h, Wk_l, nullptr, kt_h, kt_l, bk, nullptr, nullptr,
        C, CH, (size_t)N * C, 0, (size_t)N * CH, 0, F_SPLIT | F_BCOL);
    // v[c][n] = Wv . Vt^T + bv[c]  (A unbatched)
    tgemm_kernel<<<dim3(N / 256, C / 128, B), 256, TG_SMEM>>>(
        Wv_h, Wv_l, Vt_h, Vt_l, nullptr, v_h, v_l, bv, nullptr, nullptr,
        C, N, 0, (size_t)N * C, (size_t)C * N, 0, F_SPLIT | F_BROW);

    // e[n][m] = qt . kt^T  (f32 out)
    tgemm_kernel<<<dim3(N / 256, N / 128, B), 256, TG_SMEM>>>(
        qt_h, qt_l, kt_h, kt_l, e, nullptr, nullptr, nullptr, nullptr, nullptr,
        CH, N, (size_t)N * CH, (size_t)N * CH, (size_t)N * N, 0, 0);

    // attention = softmax_m(e) -> bf16 hi/lo
    softmax_row<<<dim3(N, B), 256>>>(e, a_h, a_l, N);

    // out[c][n] = gamma * (v . attn^T) + V
    tgemm_kernel<<<dim3(N / 256, C / 128, B), 256, TG_SMEM>>>(
        v_h, v_l, a_h, a_l, out, nullptr, nullptr, nullptr, V, gamma,
        N, N, (size_t)C * N, (size_t)N * N, (size_t)C * N, (size_t)C * N, F_RES);
}

// round 8
// speedup vs baseline: 4.9081x; 1.2158x over previous
#include <cuda_runtime.h>
#include <cuda_bf16.h>
#include <cuda_fp16.h>
#include <cstdint>

// ---------------------------------------------------------------------------
// AttentionModule via mma.sync m16n8k16 (HMMA; tcgen05 is ptxas-gated off).
// Energy path: bf16 split-3 (hi*hi + hi*lo + lo*hi), fp32 accum.
// Output path: attention stored as SINGLE f16 (a in [0,1], rel err 2^-11),
//   v as f16 hi/lo split-2 -> out-GEMM needs only 2 mma passes.
// Launch order puts the energy GEMM at profile slot 5 (ncu -s 5 -c 1).
// ---------------------------------------------------------------------------

static const int B_ = 4, C_ = 512, CH_ = 256, N_ = 4096;

// ---------------- scratch ----------------
__device__ __align__(256) __nv_bfloat16 g_Qt_h[4L * 4096 * 512];
__device__ __align__(256) __nv_bfloat16 g_Qt_l[4L * 4096 * 512];
__device__ __align__(256) __nv_bfloat16 g_Kt_h[4L * 4096 * 512];
__device__ __align__(256) __nv_bfloat16 g_Kt_l[4L * 4096 * 512];
__device__ __align__(256) __nv_bfloat16 g_Vt_h[4L * 4096 * 512];
__device__ __align__(256) __nv_bfloat16 g_Vt_l[4L * 4096 * 512];
__device__ __align__(256) __nv_bfloat16 g_Wq_h[256 * 512];
__device__ __align__(256) __nv_bfloat16 g_Wq_l[256 * 512];
__device__ __align__(256) __nv_bfloat16 g_Wk_h[256 * 512];
__device__ __align__(256) __nv_bfloat16 g_Wk_l[256 * 512];
__device__ __align__(256) __nv_bfloat16 g_Wv_h[512 * 512];
__device__ __align__(256) __nv_bfloat16 g_Wv_l[512 * 512];
__device__ __align__(256) __nv_bfloat16 g_qt_h[4L * 4096 * 256];
__device__ __align__(256) __nv_bfloat16 g_qt_l[4L * 4096 * 256];
__device__ __align__(256) __nv_bfloat16 g_kt_h[4L * 4096 * 256];
__device__ __align__(256) __nv_bfloat16 g_kt_l[4L * 4096 * 256];
__device__ __align__(256) __half         g_v_h [4L * 512 * 4096];
__device__ __align__(256) __half         g_v_l [4L * 512 * 4096];
__device__ __align__(256) float          g_e   [4L * 4096 * 4096];
__device__ __align__(256) __half         g_a   [4L * 4096 * 4096];

// ---------------- helpers ----------------
__device__ __forceinline__ uint32_t smem_to_u32(const void* p) {
    uint32_t a;
    asm("{ .reg .u64 t; cvta.to.shared.u64 t, %1; cvt.u32.u64 %0, t; }" : "=r"(a) : "l"(p));
    return a;
}
__device__ __forceinline__ void cp16(uint32_t dst, const void* src) {
    asm volatile("cp.async.cg.shared.global [%0], [%1], 16;" :: "r"(dst), "l"(src) : "memory");
}
__device__ __forceinline__ void cp_commit() { asm volatile("cp.async.commit_group;" ::: "memory"); }
__device__ __forceinline__ void cp_wait1()  { asm volatile("cp.async.wait_group 1;" ::: "memory"); }
__device__ __forceinline__ void cp_wait0()  { asm volatile("cp.async.wait_group 0;" ::: "memory"); }

__device__ __forceinline__ void ldsm4(uint32_t* r, uint32_t a) {
    asm volatile("ldmatrix.sync.aligned.m8n8.x4.shared.b16 {%0,%1,%2,%3}, [%4];"
                 : "=r"(r[0]), "=r"(r[1]), "=r"(r[2]), "=r"(r[3]) : "r"(a));
}
__device__ __forceinline__ void mma_bf16(float* c, const uint32_t* a, const uint32_t* b) {
    asm volatile("mma.sync.aligned.m16n8k16.row.col.f32.bf16.bf16.f32 "
                 "{%0,%1,%2,%3}, {%4,%5,%6,%7}, {%8,%9}, {%0,%1,%2,%3};"
                 : "+f"(c[0]), "+f"(c[1]), "+f"(c[2]), "+f"(c[3])
                 : "r"(a[0]), "r"(a[1]), "r"(a[2]), "r"(a[3]), "r"(b[0]), "r"(b[1]));
}
__device__ __forceinline__ void mma_f16(float* c, const uint32_t* a, const uint32_t* b) {
    asm volatile("mma.sync.aligned.m16n8k16.row.col.f32.f16.f16.f32 "
                 "{%0,%1,%2,%3}, {%4,%5,%6,%7}, {%8,%9}, {%0,%1,%2,%3};"
                 : "+f"(c[0]), "+f"(c[1]), "+f"(c[2]), "+f"(c[3])
                 : "r"(a[0]), "r"(a[1]), "r"(a[2]), "r"(a[3]), "r"(b[0]), "r"(b[1]));
}

// ---------------------------------------------------------------------------
// bf16 split-3 tgemm: D[i][j] = sum_k (Ah+Al)[i][k]*(Bh+Bl)[j][k]
// CTA tile 128x256, warp tile 64x64, K-chunk 32, double buffer, LDR=80 pad.
// ---------------------------------------------------------------------------
#define LDR     80
#define A_TILE  (128 * LDR)
#define B_TILE  (256 * LDR)
#define STAGE_S (2 * A_TILE + 2 * B_TILE)   // 61440
#define TG_SMEM (2 * STAGE_S)               // 122880

enum { F_SPLIT = 1, F_BROW = 2, F_BCOL = 4, F_RES = 8, F_F16S = 16 };

__global__ void __launch_bounds__(256, 1)
tgemm_kernel(const __nv_bfloat16* __restrict__ Ah, const __nv_bfloat16* __restrict__ Al,
             const __nv_bfloat16* __restrict__ Bh, const __nv_bfloat16* __restrict__ Bl,
             float* __restrict__ Cf, __nv_bfloat16* __restrict__ Chi, __nv_bfloat16* __restrict__ Clo,
             const float* __restrict__ bias,
             int Kd, int ldc, size_t sA, size_t sB, size_t sC, int flags)
{
    extern __shared__ char smem[];
    const uint32_t sm0 = smem_to_u32(smem);
    const int tid = threadIdx.x, wid = tid >> 5, lane = tid & 31;
    const int bz = blockIdx.z;
    const int m0 = blockIdx.y * 128;
    const int n0 = blockIdx.x * 256;

    const size_t ldkB = (size_t)Kd * 2;
    const int lr = tid >> 2, seg = tid & 3;
    const char* gA_h = (const char*)(Ah + (size_t)bz * sA) + (size_t)(m0 + lr) * ldkB + seg * 16;
    const char* gA_l = (const char*)(Al + (size_t)bz * sA) + (size_t)(m0 + lr) * ldkB + seg * 16;
    const char* gB_h = (const char*)(Bh + (size_t)bz * sB) + (size_t)(n0 + lr) * ldkB + seg * 16;
    const char* gB_l = (const char*)(Bl + (size_t)bz * sB) + (size_t)(n0 + lr) * ldkB + seg * 16;
    const size_t g64 = 64 * ldkB;
    const uint32_t dthr = sm0 + (uint32_t)lr * LDR + (uint32_t)seg * 16;

    const int nch = Kd >> 5;
    const int wm = wid & 1;
    const int wncol = (wid >> 1) * 64;
    const uint32_t a_off = (uint32_t)((lane & 15) * LDR + (lane >> 4) * 16);
    const uint32_t b_off = (uint32_t)(((lane & 7) + ((lane >> 4) & 1) * 8) * LDR + ((lane >> 3) & 1) * 16);

    float acc[4][8][4];
    #pragma unroll
    for (int i = 0; i < 4; i++)
        #pragma unroll
        for (int j = 0; j < 8; j++)
            #pragma unroll
            for (int k = 0; k < 4; k++) acc[i][j][k] = 0.f;

#define TG_LOAD(s, c) do { \
        const size_t _ko = (size_t)(c) * 64; \
        const uint32_t _d = dthr + (uint32_t)(s) * STAGE_S; \
        cp16(_d,                     gA_h + _ko); \
        cp16(_d + 64 * LDR,          gA_h + _ko + g64); \
        cp16(_d + A_TILE,            gA_l + _ko); \
        cp16(_d + A_TILE + 64 * LDR, gA_l + _ko + g64); \
        _Pragma("unroll") \
        for (int _j = 0; _j < 4; _j++) \
            cp16(_d + 2 * A_TILE + _j * 64 * LDR, gB_h + _ko + _j * g64); \
        _Pragma("unroll") \
        for (int _j = 0; _j < 4; _j++) \
            cp16(_d + 2 * A_TILE + B_TILE + _j * 64 * LDR, gB_l + _ko + _j * g64); \
        cp_commit(); \
    } while (0)

    TG_LOAD(0, 0);

    for (int c = 0; c < nch; c++) {
        const int s = c & 1;
        if (c + 1 < nch) { TG_LOAD(s ^ 1, c + 1); cp_wait1(); }
        else             { cp_wait0(); }
        __syncthreads();

        const uint32_t sb  = sm0 + (uint32_t)s * STAGE_S;
        const uint32_t sAh = sb, sAl = sb + A_TILE;
        const uint32_t sBh = sb + 2 * A_TILE, sBl = sBh + B_TILE;

        #pragma unroll
        for (int ks = 0; ks < 2; ks++) {
            const uint32_t ko = ks * 32;
            uint32_t bh[8][2], bl[8][2], af[4][4];
            #pragma unroll
            for (int p = 0; p < 4; p++) {
                uint32_t r[4];
                ldsm4(r, sBh + (uint32_t)(wncol + p * 16) * LDR + ko + b_off);
                bh[2 * p][0] = r[0]; bh[2 * p][1] = r[1];
                bh[2 * p + 1][0] = r[2]; bh[2 * p + 1][1] = r[3];
            }
            #pragma unroll
            for (int mt = 0; mt < 4; mt++)
                ldsm4(af[mt], sAh + (uint32_t)(wm * 64 + mt * 16) * LDR + ko + a_off);
            #pragma unroll
            for (int mt = 0; mt < 4; mt++)
                #pragma unroll
                for (int nt = 0; nt < 8; nt++) mma_bf16(acc[mt][nt], af[mt], bh[nt]);
            #pragma unroll
            for (int p = 0; p < 4; p++) {
                uint32_t r[4];
                ldsm4(r, sBl + (uint32_t)(wncol + p * 16) * LDR + ko + b_off);
                bl[2 * p][0] = r[0]; bl[2 * p][1] = r[1];
                bl[2 * p + 1][0] = r[2]; bl[2 * p + 1][1] = r[3];
            }
            #pragma unroll
            for (int mt = 0; mt < 4; mt++)
                #pragma unroll
                for (int nt = 0; nt < 8; nt++) mma_bf16(acc[mt][nt], af[mt], bl[nt]);
            #pragma unroll
            for (int mt = 0; mt < 4; mt++)
                ldsm4(af[mt], sAl + (uint32_t)(wm * 64 + mt * 16) * LDR + ko + a_off);
            #pragma unroll
            for (int mt = 0; mt < 4; mt++)
                #pragma unroll
                for (int nt = 0; nt < 8; nt++) mma_bf16(acc[mt][nt], af[mt], bh[nt]);
        }
        __syncthreads();
    }

    // ---------------- epilogue ----------------
    #pragma unroll
    for (int mt = 0; mt < 4; mt++) {
        #pragma unroll
        for (int h = 0; h < 2; h++) {
            const int row = m0 + wm * 64 + mt * 16 + (lane >> 2) + h * 8;
            const float br = (flags & F_BROW) ? bias[row] : 0.f;
            #pragma unroll
            for (int nt = 0; nt < 8; nt++) {
                const int col = n0 + wncol + nt * 8 + (lane & 3) * 2;
                float v0 = acc[mt][nt][h * 2 + 0];
                float v1 = acc[mt][nt][h * 2 + 1];
                if (flags & F_BCOL) { v0 += bias[col]; v1 += bias[col + 1]; }
                else                { v0 += br;        v1 += br; }
                const size_t idx = (size_t)row * ldc + col;
                if (flags & F_SPLIT) {
                    uint32_t hp, lp;
                    if (flags & F_F16S) {
                        __half h0 = __float2half_rn(v0);
                        __half h1 = __float2half_rn(v1);
                        __half l0 = __float2half_rn(v0 - __half2float(h0));
                        __half l1 = __float2half_rn(v1 - __half2float(h1));
                        hp = (uint32_t)__half_as_ushort(h0) | ((uint32_t)__half_as_ushort(h1) << 16);
                        lp = (uint32_t)__half_as_ushort(l0) | ((uint32_t)__half_as_ushort(l1) << 16);
                    } else {
                        __nv_bfloat16 h0 = __float2bfloat16_rn(v0);
                        __nv_bfloat16 h1 = __float2bfloat16_rn(v1);
                        __nv_bfloat16 l0 = __float2bfloat16_rn(v0 - __bfloat162float(h0));
                        __nv_bfloat16 l1 = __float2bfloat16_rn(v1 - __bfloat162float(h1));
                        hp = (uint32_t)__bfloat16_as_ushort(h0) | ((uint32_t)__bfloat16_as_ushort(h1) << 16);
                        lp = (uint32_t)__bfloat16_as_ushort(l0) | ((uint32_t)__bfloat16_as_ushort(l1) << 16);
                    }
                    *(uint32_t*)(Chi + (size_t)bz * sC + idx) = hp;
                    *(uint32_t*)(Clo + (size_t)bz * sC + idx) = lp;
                } else {
                    float2 o;
                    o.x = v0;
                    o.y = v1;
                    *(float2*)(Cf + (size_t)bz * sC + idx) = o;
                }
            }
        }
    }
}

// ---------------------------------------------------------------------------
// f16 out-GEMM: D = (Ah+Al) . B^T, 2 passes (A split-2 f16, B single f16).
// Epilogue: out = gamma*acc + R. Same tiling as tgemm_kernel.
// ---------------------------------------------------------------------------
#define H_STAGE (2 * A_TILE + B_TILE)   // 40960
#define H_SMEM  (2 * H_STAGE)           // 81920

__global__ void __launch_bounds__(256, 1)
tgemm_half_kernel(const __half* __restrict__ Ah, const __half* __restrict__ Al,
                  const __half* __restrict__ Bs,
                  float* __restrict__ Cf, const float* __restrict__ R,
                  const float* __restrict__ gammap,
                  int Kd, int ldc, size_t sA, size_t sB, size_t sC, size_t sR)
{
    extern __shared__ char smem[];
    const uint32_t sm0 = smem_to_u32(smem);
    const int tid = threadIdx.x, wid = tid >> 5, lane = tid & 31;
    const int bz = blockIdx.z;
    const int m0 = blockIdx.y * 128;
    const int n0 = blockIdx.x * 256;

    const size_t ldkB = (size_t)Kd * 2;
    const int lr = tid >> 2, seg = tid & 3;
    const char* gA_h = (const char*)(Ah + (size_t)bz * sA) + (size_t)(m0 + lr) * ldkB + seg * 16;
    const char* gA_l = (const char*)(Al + (size_t)bz * sA) + (size_t)(m0 + lr) * ldkB + seg * 16;
    const char* gB   = (const char*)(Bs + (size_t)bz * sB) + (size_t)(n0 + lr) * ldkB + seg * 16;
    const size_t g64 = 64 * ldkB;
    const uint32_t dthr = sm0 + (uint32_t)lr * LDR + (uint32_t)seg * 16;

    const int nch = Kd >> 5;
    const int wm = wid & 1;
    const int wncol = (wid >> 1) * 64;
    const uint32_t a_off = (uint32_t)((lane & 15) * LDR + (lane >> 4) * 16);
    const uint32_t b_off = (uint32_t)(((lane & 7) + ((lane >> 4) & 1) * 8) * LDR + ((lane >> 3) & 1) * 16);

    float acc[4][8][4];
    #pragma unroll
    for (int i = 0; i < 4; i++)
        #pragma unroll
        for (int j = 0; j < 8; j++)
            #pragma unroll
            for (int k = 0; k < 4; k++) acc[i][j][k] = 0.f;

#define TH_LOAD(s, c) do { \
        const size_t _ko = (size_t)(c) * 64; \
        const uint32_t _d = dthr + (uint32_t)(s) * H_STAGE; \
        cp16(_d,                     gA_h + _ko); \
        cp16(_d + 64 * LDR,          gA_h + _ko + g64); \
        cp16(_d + A_TILE,            gA_l + _ko); \
        cp16(_d + A_TILE + 64 * LDR, gA_l + _ko + g64); \
        _Pragma("unroll") \
        for (int _j = 0; _j < 4; _j++) \
            cp16(_d + 2 * A_TILE + _j * 64 * LDR, gB + _ko + _j * g64); \
        cp_commit(); \
    } while (0)

    TH_LOAD(0, 0);

    for (int c = 0; c < nch; c++) {
        const int s = c & 1;
        if (c + 1 < nch) { TH_LOAD(s ^ 1, c + 1); cp_wait1(); }
        else             { cp_wait0(); }
        __syncthreads();

        const uint32_t sb  = sm0 + (uint32_t)s * H_STAGE;
        const uint32_t sAh = sb, sAl = sb + A_TILE, sB_ = sb + 2 * A_TILE;

        #pragma unroll
        for (int ks = 0; ks < 2; ks++) {
            const uint32_t ko = ks * 32;
            uint32_t bf[8][2], af[4][4];
            #pragma unroll
            for (int p = 0; p < 4; p++) {
                uint32_t r[4];
                ldsm4(r, sB_ + (uint32_t)(wncol + p * 16) * LDR + ko + b_off);
                bf[2 * p][0] = r[0]; bf[2 * p][1] = r[1];
                bf[2 * p + 1][0] = r[2]; bf[2 * p + 1][1] = r[3];
            }
            #pragma unroll
            for (int mt = 0; mt < 4; mt++)
                ldsm4(af[mt], sAh + (uint32_t)(wm * 64 + mt * 16) * LDR + ko + a_off);
            #pragma unroll
            for (int mt = 0; mt < 4; mt++)
                #pragma unroll
                for (int nt = 0; nt < 8; nt++) mma_f16(acc[mt][nt], af[mt], bf[nt]);
            #pragma unroll
            for (int mt = 0; mt < 4; mt++)
                ldsm4(af[mt], sAl + (uint32_t)(wm * 64 + mt * 16) * LDR + ko + a_off);
            #pragma unroll
            for (int mt = 0; mt < 4; mt++)
                #pragma unroll
                for (int nt = 0; nt < 8; nt++) mma_f16(acc[mt][nt], af[mt], bf[nt]);
        }
        __syncthreads();
    }

    const float g = *gammap;
    #pragma unroll
    for (int mt = 0; mt < 4; mt++) {
        #pragma unroll
        for (int h = 0; h < 2; h++) {
            const int row = m0 + wm * 64 + mt * 16 + (lane >> 2) + h * 8;
            #pragma unroll
            for (int nt = 0; nt < 8; nt++) {
                const int col = n0 + wncol + nt * 8 + (lane & 3) * 2;
                const size_t idx = (size_t)row * ldc + col;
                const float2 rv = *(const float2*)(R + (size_t)bz * sR + idx);
                float2 o;
                o.x = g * acc[mt][nt][h * 2 + 0] + rv.x;
                o.y = g * acc[mt][nt][h * 2 + 1] + rv.y;
                *(float2*)(Cf + (size_t)bz * sC + idx) = o;
            }
        }
    }
}

// ---------------------------------------------------------------------------
// fused weight split (Wq, Wk, Wv in one launch)
// ---------------------------------------------------------------------------
__global__ void prep_split(const float* __restrict__ Wq, const float* __restrict__ Wk,
                           const float* __restrict__ Wv,
                           __nv_bfloat16* __restrict__ Wq_h, __nv_bfloat16* __restrict__ Wq_l,
                           __nv_bfloat16* __restrict__ Wk_h, __nv_bfloat16* __restrict__ Wk_l,
                           __nv_bfloat16* __restrict__ Wv_h, __nv_bfloat16* __restrict__ Wv_l)
{
    const int i = blockIdx.x * blockDim.x + threadIdx.x;
    const int nqk = 256 * 512;
    const float* src;
    __nv_bfloat16 *H, *L;
    int j = i;
    if (i < nqk)               { src = Wq; H = Wq_h; L = Wq_l; }
    else if (i < 2 * nqk)      { src = Wk; H = Wk_h; L = Wk_l; j = i - nqk; }
    else if (i < 2 * nqk + 512 * 512) { src = Wv; H = Wv_h; L = Wv_l; j = i - 2 * nqk; }
    else return;
    const float v = src[j];
    const __nv_bfloat16 h = __float2bfloat16_rn(v);
    H[j] = h;
    L[j] = __float2bfloat16_rn(v - __bfloat162float(h));
}

// ---------------------------------------------------------------------------
// fused transpose+split (Q, K, V in one launch): [C][N] f32 -> [N][C] bf16 hi/lo
// ---------------------------------------------------------------------------
__global__ __launch_bounds__(256)
void transpose_all(const float* __restrict__ Q, const float* __restrict__ Kin,
                   const float* __restrict__ V,
                   __nv_bfloat16* __restrict__ Qh, __nv_bfloat16* __restrict__ Ql,
                   __nv_bfloat16* __restrict__ Kh, __nv_bfloat16* __restrict__ Kl,
                   __nv_bfloat16* __restrict__ Vh, __nv_bfloat16* __restrict__ Vl,
                   int rows, int cols, int batch)
{
    __shared__ float t[32][33];
    const int z = blockIdx.z;
    const int tsel = z / batch, bz = z % batch;
    const float* X = (tsel == 0) ? Q : (tsel == 1) ? Kin : V;
    __nv_bfloat16* Th = (tsel == 0) ? Qh : (tsel == 1) ? Kh : Vh;
    __nv_bfloat16* Tl = (tsel == 0) ? Ql : (tsel == 1) ? Kl : Vl;
    const size_t bo = (size_t)bz * rows * cols;
    X += bo; Th += bo; Tl += bo;
    const int x0 = blockIdx.x * 32;
    const int y0 = blockIdx.y * 32;
    const int tx = threadIdx.x & 31, ty = threadIdx.x >> 5;

    #pragma unroll
    for (int j = 0; j < 32; j += 8)
        t[ty + j][tx] = X[(size_t)(y0 + ty + j) * cols + x0 + tx];
    __syncthreads();
    #pragma unroll
    for (int j = 0; j < 32; j += 8) {
        const float v = t[tx][ty + j];
        const __nv_bfloat16 h = __float2bfloat16_rn(v);
        const __nv_bfloat16 l = __float2bfloat16_rn(v - __bfloat162float(h));
        const size_t idx = (size_t)(x0 + ty + j) * rows + y0 + tx;
        Th[idx] = h;
        Tl[idx] = l;
    }
}

// ---------------------------------------------------------------------------
// row softmax over e [.][4096]; writes attention as SINGLE f16
// ---------------------------------------------------------------------------
__device__ __forceinline__ float fexp(float x) {  // exp(x), x <= 0
    float t = fmaxf(x * 1.44269504f, -126.f);
    float fi = floorf(t);
    float f = t - fi;
    float p = 1.5465324e-4f;
    p = p * f + 1.3333558e-3f;
    p = p * f + 9.6181291e-3f;
    p = p * f + 5.5504109e-2f;
    p = p * f + 2.4022651e-1f;
    p = p * f + 6.9314718e-1f;
    p = p * f + 1.0f;
    return p * __int_as_float(((int)fi + 127) << 23);
}

__global__ __launch_bounds__(256)
void softmax_row(const float* __restrict__ E, __half* __restrict__ A, int Ncols)
{
    const int row = blockIdx.x;
    const int bz = blockIdx.y;
    const size_t base = ((size_t)bz * gridDim.x + row) * Ncols;
    const int tid = threadIdx.x, wid = tid >> 5, lid = tid & 31;

    __shared__ float sbuf[8];

    float x[16];
    const float4* rp = (const float4*)(E + base);
    #pragma unroll
    for (int k = 0; k < 4; k++) {
        float4 v4 = rp[tid + k * 256];
        x[k * 4 + 0] = v4.x; x[k * 4 + 1] = v4.y; x[k * 4 + 2] = v4.z; x[k * 4 + 3] = v4.w;
    }

    float m = x[0];
    #pragma unroll
    for (int i = 1; i < 16; i++) m = fmaxf(m, x[i]);
    #pragma unroll
    for (int o = 16; o; o >>= 1) m = fmaxf(m, __shfl_xor_sync(0xffffffffu, m, o));
    if (lid == 0) sbuf[wid] = m;
    __syncthreads();
    float mx = sbuf[0];
    #pragma unroll
    for (int i = 1; i < 8; i++) mx = fmaxf(mx, sbuf[i]);
    __syncthreads();

    float s = 0.f;
    #pragma unroll
    for (int i = 0; i < 16; i++) { x[i] = fexp(x[i] - mx); s += x[i]; }
    #pragma unroll
    for (int o = 16; o; o >>= 1) s += __shfl_xor_sync(0xffffffffu, s, o);
    if (lid == 0) sbuf[wid] = s;
    __syncthreads();
    float tot = 0.f;
    #pragma unroll
    for (int i = 0; i < 8; i++) tot += sbuf[i];
    const float inv = 1.f / tot;

    #pragma unroll
    for (int k = 0; k < 4; k++) {
        uint32_t hp[2];
        #pragma unroll
        for (int j = 0; j < 2; j++) {
            __half2 p2 = __floats2half2_rn(x[k * 4 + 2 * j] * inv, x[k * 4 + 2 * j + 1] * inv);
            hp[j] = *(uint32_t*)&p2;
        }
        const size_t idx = base + (size_t)(tid + k * 256) * 4;
        *(uint2*)(A + idx) = *(const uint2*)hp;
    }
}

// ---------------------------------------------------------------------------
extern "C" void kernel_launch(void* const* d_in, const int* in_sizes, int n_in,
                              void* d_out, int out_size)
{
    const float* Q     = (const float*)d_in[0];
    const float* Kin   = (const float*)d_in[1];
    const float* V     = (const float*)d_in[2];
    const float* Wq    = (const float*)d_in[3];
    const float* bq    = (const float*)d_in[4];
    const float* Wk    = (const float*)d_in[5];
    const float* bk    = (const float*)d_in[6];
    const float* Wv    = (const float*)d_in[7];
    const float* bv    = (const float*)d_in[8];
    const float* gamma = (const float*)d_in[9];
    float* out = (float*)d_out;

    __nv_bfloat16 *Qt_h, *Qt_l, *Kt_h, *Kt_l, *Vt_h, *Vt_l;
    __nv_bfloat16 *Wq_h, *Wq_l, *Wk_h, *Wk_l, *Wv_h, *Wv_l;
    __nv_bfloat16 *qt_h, *qt_l, *kt_h, *kt_l;
    __half *v_h, *v_l, *a;
    float* e;
    cudaGetSymbolAddress((void**)&Qt_h, g_Qt_h); cudaGetSymbolAddress((void**)&Qt_l, g_Qt_l);
    cudaGetSymbolAddress((void**)&Kt_h, g_Kt_h); cudaGetSymbolAddress((void**)&Kt_l, g_Kt_l);
    cudaGetSymbolAddress((void**)&Vt_h, g_Vt_h); cudaGetSymbolAddress((void**)&Vt_l, g_Vt_l);
    cudaGetSymbolAddress((void**)&Wq_h, g_Wq_h); cudaGetSymbolAddress((void**)&Wq_l, g_Wq_l);
    cudaGetSymbolAddress((void**)&Wk_h, g_Wk_h); cudaGetSymbolAddress((void**)&Wk_l, g_Wk_l);
    cudaGetSymbolAddress((void**)&Wv_h, g_Wv_h); cudaGetSymbolAddress((void**)&Wv_l, g_Wv_l);
    cudaGetSymbolAddress((void**)&qt_h, g_qt_h); cudaGetSymbolAddress((void**)&qt_l, g_qt_l);
    cudaGetSymbolAddress((void**)&kt_h, g_kt_h); cudaGetSymbolAddress((void**)&kt_l, g_kt_l);
    cudaGetSymbolAddress((void**)&v_h,  g_v_h);  cudaGetSymbolAddress((void**)&v_l,  g_v_l);
    cudaGetSymbolAddress((void**)&a,    g_a);
    cudaGetSymbolAddress((void**)&e,    g_e);

    const int B = B_, C = C_, CH = CH_, N = N_;

    cudaFuncSetAttribute(tgemm_kernel, cudaFuncAttributeMaxDynamicSharedMemorySize, TG_SMEM);
    cudaFuncSetAttribute(tgemm_half_kernel, cudaFuncAttributeMaxDynamicSharedMemorySize, H_SMEM);

    // launch 0: weight splits (fused)
    const int nsplit = 2 * CH * C + C * C;
    prep_split<<<(nsplit + 255) / 256, 256>>>(Wq, Wk, Wv, Wq_h, Wq_l, Wk_h, Wk_l, Wv_h, Wv_l);

    // launch 1: input transpose+split (fused)
    transpose_all<<<dim3(N / 32, C / 32, 3 * B), 256>>>(
        Q, Kin, V, Qt_h, Qt_l, Kt_h, Kt_l, Vt_h, Vt_l, C, N, B);

    // launch 2: qt[n][ch] = Qt . Wq^T + bq[ch]  (bf16 split out)
    tgemm_kernel<<<dim3(CH / 256, N / 128, B), 256, TG_SMEM>>>(
        Qt_h, Qt_l, Wq_h, Wq_l, nullptr, qt_h, qt_l, bq,
        C, CH, (size_t)N * C, 0, (size_t)N * CH, F_SPLIT | F_BCOL);
    // launch 3: kt
    tgemm_kernel<<<dim3(CH / 256, N / 128, B), 256, TG_SMEM>>>(
        Kt_h, Kt_l, Wk_h, Wk_l, nullptr, kt_h, kt_l, bk,
        C, CH, (size_t)N * C, 0, (size_t)N * CH, F_SPLIT | F_BCOL);
    // launch 4: v[c][n] = Wv . Vt^T + bv[c]  (f16 split out)
    tgemm_kernel<<<dim3(N / 256, C / 128, B), 256, TG_SMEM>>>(
        Wv_h, Wv_l, Vt_h, Vt_l, nullptr,
        (__nv_bfloat16*)v_h, (__nv_bfloat16*)v_l, bv,
        C, N, 0, (size_t)N * C, (size_t)C * N, F_SPLIT | F_BROW | F_F16S);

    // launch 5 (profiled): e[n][m] = qt . kt^T  (f32 out)
    tgemm_kernel<<<dim3(N / 256, N / 128, B), 256, TG_SMEM>>>(
        qt_h, qt_l, kt_h, kt_l, e, nullptr, nullptr, nullptr,
        CH, N, (size_t)N * CH, (size_t)N * CH, (size_t)N * N, 0);

    // launch 6: attention = softmax_m(e) -> single f16
    softmax_row<<<dim3(N, B), 256>>>(e, a, N);

    // launch 7: out[c][n] = gamma * (v . attn^T) + V   (2-pass f16)
    tgemm_half_kernel<<<dim3(N / 256, C / 128, B), 256, H_SMEM>>>(
        v_h, v_l, a, out, V, gamma,
        N, N, (size_t)C * N, (size_t)N * N, (size_t)C * N, (size_t)C * N);
}

// round 10
// speedup vs baseline: 6.0202x; 1.2266x over previous
#include <cuda_runtime.h>
#include <cuda_bf16.h>
#include <cuda_fp16.h>
#include <cstdint>

// ---------------------------------------------------------------------------
// AttentionModule via mma.sync m16n8k16 (legacy HMMA; tcgen05 ptxas-gated off;
// measured HW cap ~585 MACs/cyc/SM => minimize mma PASSES, not tiles).
//   q/k projections: bf16 split-3 (needs 2^-16: logits amplify errors x16)
//   v projection:    f16, Wv split-2 x Vt single  -> 2 passes, v stored f16
//   energy:          bf16 split-3, f32 out
//   softmax:         poly-exp, whole row in regs, a stored single f16
//   out:             SINGLE-pass f16 (v f16 x a f16), epilogue gamma*acc + V
// ---------------------------------------------------------------------------

static const int B_ = 4, C_ = 512, CH_ = 256, N_ = 4096;

// ---------------- scratch ----------------
__device__ __align__(256) __nv_bfloat16 g_Qt_h[4L * 4096 * 512];
__device__ __align__(256) __nv_bfloat16 g_Qt_l[4L * 4096 * 512];
__device__ __align__(256) __nv_bfloat16 g_Kt_h[4L * 4096 * 512];
__device__ __align__(256) __nv_bfloat16 g_Kt_l[4L * 4096 * 512];
__device__ __align__(256) __half        g_Vt  [4L * 4096 * 512];
__device__ __align__(256) __nv_bfloat16 g_Wq_h[256 * 512];
__device__ __align__(256) __nv_bfloat16 g_Wq_l[256 * 512];
__device__ __align__(256) __nv_bfloat16 g_Wk_h[256 * 512];
__device__ __align__(256) __nv_bfloat16 g_Wk_l[256 * 512];
__device__ __align__(256) __half        g_Wv_h[512 * 512];
__device__ __align__(256) __half        g_Wv_l[512 * 512];
__device__ __align__(256) __nv_bfloat16 g_qt_h[4L * 4096 * 256];
__device__ __align__(256) __nv_bfloat16 g_qt_l[4L * 4096 * 256];
__device__ __align__(256) __nv_bfloat16 g_kt_h[4L * 4096 * 256];
__device__ __align__(256) __nv_bfloat16 g_kt_l[4L * 4096 * 256];
__device__ __align__(256) __half        g_v   [4L * 512 * 4096];
__device__ __align__(256) float         g_e   [4L * 4096 * 4096];
__device__ __align__(256) __half        g_a   [4L * 4096 * 4096];

// ---------------- helpers ----------------
__device__ __forceinline__ uint32_t smem_to_u32(const void* p) {
    uint32_t a;
    asm("{ .reg .u64 t; cvta.to.shared.u64 t, %1; cvt.u32.u64 %0, t; }" : "=r"(a) : "l"(p));
    return a;
}
__device__ __forceinline__ void cp16(uint32_t dst, const void* src) {
    asm volatile("cp.async.cg.shared.global [%0], [%1], 16;" :: "r"(dst), "l"(src) : "memory");
}
__device__ __forceinline__ void cp_commit() { asm volatile("cp.async.commit_group;" ::: "memory"); }
__device__ __forceinline__ void cp_wait1()  { asm volatile("cp.async.wait_group 1;" ::: "memory"); }
__device__ __forceinline__ void cp_wait0()  { asm volatile("cp.async.wait_group 0;" ::: "memory"); }

__device__ __forceinline__ void ldsm4(uint32_t* r, uint32_t a) {
    asm volatile("ldmatrix.sync.aligned.m8n8.x4.shared.b16 {%0,%1,%2,%3}, [%4];"
                 : "=r"(r[0]), "=r"(r[1]), "=r"(r[2]), "=r"(r[3]) : "r"(a));
}
__device__ __forceinline__ void mma_bf16(float* c, const uint32_t* a, const uint32_t* b) {
    asm volatile("mma.sync.aligned.m16n8k16.row.col.f32.bf16.bf16.f32 "
                 "{%0,%1,%2,%3}, {%4,%5,%6,%7}, {%8,%9}, {%0,%1,%2,%3};"
                 : "+f"(c[0]), "+f"(c[1]), "+f"(c[2]), "+f"(c[3])
                 : "r"(a[0]), "r"(a[1]), "r"(a[2]), "r"(a[3]), "r"(b[0]), "r"(b[1]));
}
__device__ __forceinline__ void mma_f16(float* c, const uint32_t* a, const uint32_t* b) {
    asm volatile("mma.sync.aligned.m16n8k16.row.col.f32.f16.f16.f32 "
                 "{%0,%1,%2,%3}, {%4,%5,%6,%7}, {%8,%9}, {%0,%1,%2,%3};"
                 : "+f"(c[0]), "+f"(c[1]), "+f"(c[2]), "+f"(c[3])
                 : "r"(a[0]), "r"(a[1]), "r"(a[2]), "r"(a[3]), "r"(b[0]), "r"(b[1]));
}

#define LDR     80
#define A_TILE  (128 * LDR)
#define B_TILE  (256 * LDR)

enum { F_SPLIT = 1, F_BROW = 2, F_BCOL = 4, F_RES = 8 };

// ---------------------------------------------------------------------------
// bf16 split-3 tgemm (q/k projections + energy). CTA 128x256, warp 64x64.
// ---------------------------------------------------------------------------
#define STAGE_S (2 * A_TILE + 2 * B_TILE)   // 61440
#define TG_SMEM (2 * STAGE_S)               // 122880

__global__ void __launch_bounds__(256, 1)
tgemm_kernel(const __nv_bfloat16* __restrict__ Ah, const __nv_bfloat16* __restrict__ Al,
             const __nv_bfloat16* __restrict__ Bh, const __nv_bfloat16* __restrict__ Bl,
             float* __restrict__ Cf, __nv_bfloat16* __restrict__ Chi, __nv_bfloat16* __restrict__ Clo,
             const float* __restrict__ bias,
             int Kd, int ldc, size_t sA, size_t sB, size_t sC, int flags)
{
    extern __shared__ char smem[];
    const uint32_t sm0 = smem_to_u32(smem);
    const int tid = threadIdx.x, wid = tid >> 5, lane = tid & 31;
    const int bz = blockIdx.z;
    const int m0 = blockIdx.y * 128;
    const int n0 = blockIdx.x * 256;

    const size_t ldkB = (size_t)Kd * 2;
    const int lr = tid >> 2, seg = tid & 3;
    const char* gA_h = (const char*)(Ah + (size_t)bz * sA) + (size_t)(m0 + lr) * ldkB + seg * 16;
    const char* gA_l = (const char*)(Al + (size_t)bz * sA) + (size_t)(m0 + lr) * ldkB + seg * 16;
    const char* gB_h = (const char*)(Bh + (size_t)bz * sB) + (size_t)(n0 + lr) * ldkB + seg * 16;
    const char* gB_l = (const char*)(Bl + (size_t)bz * sB) + (size_t)(n0 + lr) * ldkB + seg * 16;
    const size_t g64 = 64 * ldkB;
    const uint32_t dthr = sm0 + (uint32_t)lr * LDR + (uint32_t)seg * 16;

    const int nch = Kd >> 5;
    const int wm = wid & 1;
    const int wncol = (wid >> 1) * 64;
    const uint32_t a_off = (uint32_t)((lane & 15) * LDR + (lane >> 4) * 16);
    const uint32_t b_off = (uint32_t)(((lane & 7) + ((lane >> 4) & 1) * 8) * LDR + ((lane >> 3) & 1) * 16);

    float acc[4][8][4];
    #pragma unroll
    for (int i = 0; i < 4; i++)
        #pragma unroll
        for (int j = 0; j < 8; j++)
            #pragma unroll
            for (int k = 0; k < 4; k++) acc[i][j][k] = 0.f;

#define TG_LOAD(s, c) do { \
        const size_t _ko = (size_t)(c) * 64; \
        const uint32_t _d = dthr + (uint32_t)(s) * STAGE_S; \
        cp16(_d,                     gA_h + _ko); \
        cp16(_d + 64 * LDR,          gA_h + _ko + g64); \
        cp16(_d + A_TILE,            gA_l + _ko); \
        cp16(_d + A_TILE + 64 * LDR, gA_l + _ko + g64); \
        _Pragma("unroll") \
        for (int _j = 0; _j < 4; _j++) \
            cp16(_d + 2 * A_TILE + _j * 64 * LDR, gB_h + _ko + _j * g64); \
        _Pragma("unroll") \
        for (int _j = 0; _j < 4; _j++) \
            cp16(_d + 2 * A_TILE + B_TILE + _j * 64 * LDR, gB_l + _ko + _j * g64); \
        cp_commit(); \
    } while (0)

    TG_LOAD(0, 0);

    for (int c = 0; c < nch; c++) {
        const int s = c & 1;
        if (c + 1 < nch) { TG_LOAD(s ^ 1, c + 1); cp_wait1(); }
        else             { cp_wait0(); }
        __syncthreads();

        const uint32_t sb  = sm0 + (uint32_t)s * STAGE_S;
        const uint32_t sAh = sb, sAl = sb + A_TILE;
        const uint32_t sBh = sb + 2 * A_TILE, sBl = sBh + B_TILE;

        #pragma unroll
        for (int ks = 0; ks < 2; ks++) {
            const uint32_t ko = ks * 32;
            uint32_t bh[8][2], bl[8][2], af[4][4];
            #pragma unroll
            for (int p = 0; p < 4; p++) {
                uint32_t r[4];
                ldsm4(r, sBh + (uint32_t)(wncol + p * 16) * LDR + ko + b_off);
                bh[2 * p][0] = r[0]; bh[2 * p][1] = r[1];
                bh[2 * p + 1][0] = r[2]; bh[2 * p + 1][1] = r[3];
            }
            #pragma unroll
            for (int mt = 0; mt < 4; mt++)
                ldsm4(af[mt], sAh + (uint32_t)(wm * 64 + mt * 16) * LDR + ko + a_off);
            #pragma unroll
            for (int mt = 0; mt < 4; mt++)
                #pragma unroll
                for (int nt = 0; nt < 8; nt++) mma_bf16(acc[mt][nt], af[mt], bh[nt]);
            #pragma unroll
            for (int p = 0; p < 4; p++) {
                uint32_t r[4];
                ldsm4(r, sBl + (uint32_t)(wncol + p * 16) * LDR + ko + b_off);
                bl[2 * p][0] = r[0]; bl[2 * p][1] = r[1];
                bl[2 * p + 1][0] = r[2]; bl[2 * p + 1][1] = r[3];
            }
            #pragma unroll
            for (int mt = 0; mt < 4; mt++)
                #pragma unroll
                for (int nt = 0; nt < 8; nt++) mma_bf16(acc[mt][nt], af[mt], bl[nt]);
            #pragma unroll
            for (int mt = 0; mt < 4; mt++)
                ldsm4(af[mt], sAl + (uint32_t)(wm * 64 + mt * 16) * LDR + ko + a_off);
            #pragma unroll
            for (int mt = 0; mt < 4; mt++)
                #pragma unroll
                for (int nt = 0; nt < 8; nt++) mma_bf16(acc[mt][nt], af[mt], bh[nt]);
        }
        __syncthreads();
    }

    // epilogue
    #pragma unroll
    for (int mt = 0; mt < 4; mt++) {
        #pragma unroll
        for (int h = 0; h < 2; h++) {
            const int row = m0 + wm * 64 + mt * 16 + (lane >> 2) + h * 8;
            const float br = (flags & F_BROW) ? bias[row] : 0.f;
            #pragma unroll
            for (int nt = 0; nt < 8; nt++) {
                const int col = n0 + wncol + nt * 8 + (lane & 3) * 2;
                float v0 = acc[mt][nt][h * 2 + 0];
                float v1 = acc[mt][nt][h * 2 + 1];
                if (flags & F_BCOL) { v0 += bias[col]; v1 += bias[col + 1]; }
                else                { v0 += br;        v1 += br; }
                const size_t idx = (size_t)row * ldc + col;
                if (flags & F_SPLIT) {
                    __nv_bfloat16 h0 = __float2bfloat16_rn(v0);
                    __nv_bfloat16 h1 = __float2bfloat16_rn(v1);
                    __nv_bfloat16 l0 = __float2bfloat16_rn(v0 - __bfloat162float(h0));
                    __nv_bfloat16 l1 = __float2bfloat16_rn(v1 - __bfloat162float(h1));
                    uint32_t hp = (uint32_t)__bfloat16_as_ushort(h0) | ((uint32_t)__bfloat16_as_ushort(h1) << 16);
                    uint32_t lp = (uint32_t)__bfloat16_as_ushort(l0) | ((uint32_t)__bfloat16_as_ushort(l1) << 16);
                    *(uint32_t*)(Chi + (size_t)bz * sC + idx) = hp;
                    *(uint32_t*)(Clo + (size_t)bz * sC + idx) = lp;
                } else {
                    float2 o;
                    o.x = v0;
                    o.y = v1;
                    *(float2*)(Cf + (size_t)bz * sC + idx) = o;
                }
            }
        }
    }
}

// ---------------------------------------------------------------------------
// f16 GEMM, TWO=1: D = (Ah+Al).B^T (2 passes); TWO=0: D = Ah.B^T (1 pass).
// Epilogue: F_RES -> f32 gamma*acc + R  else f16 single with row bias.
// ---------------------------------------------------------------------------
template <int TWO>
__global__ void __launch_bounds__(256, 1)
tgemm_h(const __half* __restrict__ Ah, const __half* __restrict__ Al,
        const __half* __restrict__ Bs,
        float* __restrict__ Cf, __half* __restrict__ Ch,
        const float* __restrict__ bias, const float* __restrict__ R,
        const float* __restrict__ gammap,
        int Kd, int ldc, size_t sA, size_t sB, size_t sC, size_t sR, int flags)
{
    constexpr int H_STAGE = (TWO ? 2 : 1) * A_TILE + B_TILE;
    extern __shared__ char smem[];
    const uint32_t sm0 = smem_to_u32(smem);
    const int tid = threadIdx.x, wid = tid >> 5, lane = tid & 31;
    const int bz = blockIdx.z;
    const int m0 = blockIdx.y * 128;
    const int n0 = blockIdx.x * 256;

    const size_t ldkB = (size_t)Kd * 2;
    const int lr = tid >> 2, seg = tid & 3;
    const char* gA_h = (const char*)(Ah + (size_t)bz * sA) + (size_t)(m0 + lr) * ldkB + seg * 16;
    const char* gA_l = TWO ? (const char*)(Al + (size_t)bz * sA) + (size_t)(m0 + lr) * ldkB + seg * 16 : nullptr;
    const char* gB   = (const char*)(Bs + (size_t)bz * sB) + (size_t)(n0 + lr) * ldkB + seg * 16;
    const size_t g64 = 64 * ldkB;
    const uint32_t dthr = sm0 + (uint32_t)lr * LDR + (uint32_t)seg * 16;
    const uint32_t boff_b = (TWO ? 2 : 1) * A_TILE;

    const int nch = Kd >> 5;
    const int wm = wid & 1;
    const int wncol = (wid >> 1) * 64;
    const uint32_t a_off = (uint32_t)((lane & 15) * LDR + (lane >> 4) * 16);
    const uint32_t b_off = (uint32_t)(((lane & 7) + ((lane >> 4) & 1) * 8) * LDR + ((lane >> 3) & 1) * 16);

    float acc[4][8][4];
    #pragma unroll
    for (int i = 0; i < 4; i++)
        #pragma unroll
        for (int j = 0; j < 8; j++)
            #pragma unroll
            for (int k = 0; k < 4; k++) acc[i][j][k] = 0.f;

#define TH_LOAD(s, c) do { \
        const size_t _ko = (size_t)(c) * 64; \
        const uint32_t _d = dthr + (uint32_t)(s) * H_STAGE; \
        cp16(_d,            gA_h + _ko); \
        cp16(_d + 64 * LDR, gA_h + _ko + g64); \
        if (TWO) { \
            cp16(_d + A_TILE,            gA_l + _ko); \
            cp16(_d + A_TILE + 64 * LDR, gA_l + _ko + g64); \
        } \
        _Pragma("unroll") \
        for (int _j = 0; _j < 4; _j++) \
            cp16(_d + boff_b + _j * 64 * LDR, gB + _ko + _j * g64); \
        cp_commit(); \
    } while (0)

    TH_LOAD(0, 0);

    for (int c = 0; c < nch; c++) {
        const int s = c & 1;
        if (c + 1 < nch) { TH_LOAD(s ^ 1, c + 1); cp_wait1(); }
        else             { cp_wait0(); }
        __syncthreads();

        const uint32_t sb  = sm0 + (uint32_t)s * H_STAGE;
        const uint32_t sAh = sb, sAl = sb + A_TILE, sB_ = sb + boff_b;

        #pragma unroll
        for (int ks = 0; ks < 2; ks++) {
            const uint32_t ko = ks * 32;
            uint32_t bf[8][2], af[4][4];
            #pragma unroll
            for (int p = 0; p < 4; p++) {
                uint32_t r[4];
                ldsm4(r, sB_ + (uint32_t)(wncol + p * 16) * LDR + ko + b_off);
                bf[2 * p][0] = r[0]; bf[2 * p][1] = r[1];
                bf[2 * p + 1][0] = r[2]; bf[2 * p + 1][1] = r[3];
            }
            #pragma unroll
            for (int mt = 0; mt < 4; mt++)
                ldsm4(af[mt], sAh + (uint32_t)(wm * 64 + mt * 16) * LDR + ko + a_off);
            #pragma unroll
            for (int mt = 0; mt < 4; mt++)
                #pragma unroll
                for (int nt = 0; nt < 8; nt++) mma_f16(acc[mt][nt], af[mt], bf[nt]);
            if (TWO) {
                #pragma unroll
                for (int mt = 0; mt < 4; mt++)
                    ldsm4(af[mt], sAl + (uint32_t)(wm * 64 + mt * 16) * LDR + ko + a_off);
                #pragma unroll
                for (int mt = 0; mt < 4; mt++)
                    #pragma unroll
                    for (int nt = 0; nt < 8; nt++) mma_f16(acc[mt][nt], af[mt], bf[nt]);
            }
        }
        __syncthreads();
    }

    if (flags & F_RES) {
        const float g = *gammap;
        #pragma unroll
        for (int mt = 0; mt < 4; mt++)
            #pragma unroll
            for (int h = 0; h < 2; h++) {
                const int row = m0 + wm * 64 + mt * 16 + (lane >> 2) + h * 8;
                #pragma unroll
                for (int nt = 0; nt < 8; nt++) {
                    const int col = n0 + wncol + nt * 8 + (lane & 3) * 2;
                    const size_t idx = (size_t)row * ldc + col;
                    const float2 rv = *(const float2*)(R + (size_t)bz * sR + idx);
                    float2 o;
                    o.x = g * acc[mt][nt][h * 2 + 0] + rv.x;
                    o.y = g * acc[mt][nt][h * 2 + 1] + rv.y;
                    *(float2*)(Cf + (size_t)bz * sC + idx) = o;
                }
            }
    } else {
        #pragma unroll
        for (int mt = 0; mt < 4; mt++)
            #pragma unroll
            for (int h = 0; h < 2; h++) {
                const int row = m0 + wm * 64 + mt * 16 + (lane >> 2) + h * 8;
                const float br = (flags & F_BROW) ? bias[row] : 0.f;
                #pragma unroll
                for (int nt = 0; nt < 8; nt++) {
                    const int col = n0 + wncol + nt * 8 + (lane & 3) * 2;
                    const size_t idx = (size_t)row * ldc + col;
                    __half2 p2 = __floats2half2_rn(acc[mt][nt][h * 2 + 0] + br,
                                                   acc[mt][nt][h * 2 + 1] + br);
                    *(uint32_t*)(Ch + (size_t)bz * sC + idx) = *(uint32_t*)&p2;
                }
            }
    }
}

// ---------------------------------------------------------------------------
// fused weight split: Wq/Wk -> bf16 hi/lo, Wv -> f16 hi/lo
// ---------------------------------------------------------------------------
__global__ void prep_split(const float* __restrict__ Wq, const float* __restrict__ Wk,
                           const float* __restrict__ Wv,
                           __nv_bfloat16* __restrict__ Wq_h, __nv_bfloat16* __restrict__ Wq_l,
                           __nv_bfloat16* __restrict__ Wk_h, __nv_bfloat16* __restrict__ Wk_l,
                           __half* __restrict__ Wv_h, __half* __restrict__ Wv_l)
{
    const int i = blockIdx.x * blockDim.x + threadIdx.x;
    const int nqk = 256 * 512;
    if (i < 2 * nqk) {
        const float* src = (i < nqk) ? Wq : Wk;
        __nv_bfloat16* H = (i < nqk) ? Wq_h : Wk_h;
        __nv_bfloat16* L = (i < nqk) ? Wq_l : Wk_l;
        const int j = (i < nqk) ? i : i - nqk;
        const float v = src[j];
        const __nv_bfloat16 h = __float2bfloat16_rn(v);
        H[j] = h;
        L[j] = __float2bfloat16_rn(v - __bfloat162float(h));
    } else if (i < 2 * nqk + 512 * 512) {
        const int j = i - 2 * nqk;
        const float v = Wv[j];
        const __half h = __float2half_rn(v);
        Wv_h[j] = h;
        Wv_l[j] = __float2half_rn(v - __half2float(h));
    }
}

// ---------------------------------------------------------------------------
// fused transpose: Q,K -> bf16 hi/lo [N][C]; V -> single f16 [N][C]
// ---------------------------------------------------------------------------
__global__ __launch_bounds__(256)
void transpose_all(const float* __restrict__ Q, const float* __restrict__ Kin,
                   const float* __restrict__ V,
                   __nv_bfloat16* __restrict__ Qh, __nv_bfloat16* __restrict__ Ql,
                   __nv_bfloat16* __restrict__ Kh, __nv_bfloat16* __restrict__ Kl,
                   __half* __restrict__ Vt,
                   int rows, int cols, int batch)
{
    __shared__ float t[32][33];
    const int z = blockIdx.z;
    const int tsel = z / batch, bz = z % batch;
    const float* X = (tsel == 0) ? Q : (tsel == 1) ? Kin : V;
    const size_t bo = (size_t)bz * rows * cols;
    X += bo;
    const int x0 = blockIdx.x * 32;
    const int y0 = blockIdx.y * 32;
    const int tx = threadIdx.x & 31, ty = threadIdx.x >> 5;

    #pragma unroll
    for (int j = 0; j < 32; j += 8)
        t[ty + j][tx] = X[(size_t)(y0 + ty + j) * cols + x0 + tx];
    __syncthreads();

    if (tsel < 2) {
        __nv_bfloat16* Th = ((tsel == 0) ? Qh : Kh) + bo;
        __nv_bfloat16* Tl = ((tsel == 0) ? Ql : Kl) + bo;
        #pragma unroll
        for (int j = 0; j < 32; j += 8) {
            const float v = t[tx][ty + j];
            const __nv_bfloat16 h = __float2bfloat16_rn(v);
            const __nv_bfloat16 l = __float2bfloat16_rn(v - __bfloat162float(h));
            const size_t idx = (size_t)(x0 + ty + j) * rows + y0 + tx;
            Th[idx] = h;
            Tl[idx] = l;
        }
    } else {
        __half* Tv = Vt + bo;
        #pragma unroll
        for (int j = 0; j < 32; j += 8) {
            const size_t idx = (size_t)(x0 + ty + j) * rows + y0 + tx;
            Tv[idx] = __float2half_rn(t[tx][ty + j]);
        }
    }
}

// ---------------------------------------------------------------------------
// row softmax over e [.][4096]; writes attention as single f16
// ---------------------------------------------------------------------------
__device__ __forceinline__ float fexp(float x) {  // exp(x), x <= 0
    float t = fmaxf(x * 1.44269504f, -126.f);
    float fi = floorf(t);
    float f = t - fi;
    float p = 1.5465324e-4f;
    p = p * f + 1.3333558e-3f;
    p = p * f + 9.6181291e-3f;
    p = p * f + 5.5504109e-2f;
    p = p * f + 2.4022651e-1f;
    p = p * f + 6.9314718e-1f;
    p = p * f + 1.0f;
    return p * __int_as_float(((int)fi + 127) << 23);
}

__global__ __launch_bounds__(256)
void softmax_row(const float* __restrict__ E, __half* __restrict__ A, int Ncols)
{
    const int row = blockIdx.x;
    const int bz = blockIdx.y;
    const size_t base = ((size_t)bz * gridDim.x + row) * Ncols;
    const int tid = threadIdx.x, wid = tid >> 5, lid = tid & 31;

    __shared__ float sbuf[8];

    float x[16];
    const float4* rp = (const float4*)(E + base);
    #pragma unroll
    for (int k = 0; k < 4; k++) {
        float4 v4 = rp[tid + k * 256];
        x[k * 4 + 0] = v4.x; x[k * 4 + 1] = v4.y; x[k * 4 + 2] = v4.z; x[k * 4 + 3] = v4.w;
    }

    float m = x[0];
    #pragma unroll
    for (int i = 1; i < 16; i++) m = fmaxf(m, x[i]);
    #pragma unroll
    for (int o = 16; o; o >>= 1) m = fmaxf(m, __shfl_xor_sync(0xffffffffu, m, o));
    if (lid == 0) sbuf[wid] = m;
    __syncthreads();
    float mx = sbuf[0];
    #pragma unroll
    for (int i = 1; i < 8; i++) mx = fmaxf(mx, sbuf[i]);
    __syncthreads();

    float s = 0.f;
    #pragma unroll
    for (int i = 0; i < 16; i++) { x[i] = fexp(x[i] - mx); s += x[i]; }
    #pragma unroll
    for (int o = 16; o; o >>= 1) s += __shfl_xor_sync(0xffffffffu, s, o);
    if (lid == 0) sbuf[wid] = s;
    __syncthreads();
    float tot = 0.f;
    #pragma unroll
    for (int i = 0; i < 8; i++) tot += sbuf[i];
    const float inv = 1.f / tot;

    #pragma unroll
    for (int k = 0; k < 4; k++) {
        uint32_t hp[2];
        #pragma unroll
        for (int j = 0; j < 2; j++) {
            __half2 p2 = __floats2half2_rn(x[k * 4 + 2 * j] * inv, x[k * 4 + 2 * j + 1] * inv);
            hp[j] = *(uint32_t*)&p2;
        }
        const size_t idx = base + (size_t)(tid + k * 256) * 4;
        *(uint2*)(A + idx) = *(const uint2*)hp;
    }
}

// ---------------------------------------------------------------------------
extern "C" void kernel_launch(void* const* d_in, const int* in_sizes, int n_in,
                              void* d_out, int out_size)
{
    const float* Q     = (const float*)d_in[0];
    const float* Kin   = (const float*)d_in[1];
    const float* V     = (const float*)d_in[2];
    const float* Wq    = (const float*)d_in[3];
    const float* bq    = (const float*)d_in[4];
    const float* Wk    = (const float*)d_in[5];
    const float* bk    = (const float*)d_in[6];
    const float* Wv    = (const float*)d_in[7];
    const float* bv    = (const float*)d_in[8];
    const float* gamma = (const float*)d_in[9];
    float* out = (float*)d_out;

    __nv_bfloat16 *Qt_h, *Qt_l, *Kt_h, *Kt_l;
    __half *Vt, *Wv_h, *Wv_l, *v, *a;
    __nv_bfloat16 *Wq_h, *Wq_l, *Wk_h, *Wk_l;
    __nv_bfloat16 *qt_h, *qt_l, *kt_h, *kt_l;
    float* e;
    cudaGetSymbolAddress((void**)&Qt_h, g_Qt_h); cudaGetSymbolAddress((void**)&Qt_l, g_Qt_l);
    cudaGetSymbolAddress((void**)&Kt_h, g_Kt_h); cudaGetSymbolAddress((void**)&Kt_l, g_Kt_l);
    cudaGetSymbolAddress((void**)&Vt,   g_Vt);
    cudaGetSymbolAddress((void**)&Wq_h, g_Wq_h); cudaGetSymbolAddress((void**)&Wq_l, g_Wq_l);
    cudaGetSymbolAddress((void**)&Wk_h, g_Wk_h); cudaGetSymbolAddress((void**)&Wk_l, g_Wk_l);
    cudaGetSymbolAddress((void**)&Wv_h, g_Wv_h); cudaGetSymbolAddress((void**)&Wv_l, g_Wv_l);
    cudaGetSymbolAddress((void**)&qt_h, g_qt_h); cudaGetSymbolAddress((void**)&qt_l, g_qt_l);
    cudaGetSymbolAddress((void**)&kt_h, g_kt_h); cudaGetSymbolAddress((void**)&kt_l, g_kt_l);
    cudaGetSymbolAddress((void**)&v,    g_v);
    cudaGetSymbolAddress((void**)&a,    g_a);
    cudaGetSymbolAddress((void**)&e,    g_e);

    const int B = B_, C = C_, CH = CH_, N = N_;

    cudaFuncSetAttribute(tgemm_kernel, cudaFuncAttributeMaxDynamicSharedMemorySize, TG_SMEM);
    cudaFuncSetAttribute(tgemm_h<1>, cudaFuncAttributeMaxDynamicSharedMemorySize,
                         2 * (2 * A_TILE + B_TILE));
    cudaFuncSetAttribute(tgemm_h<0>, cudaFuncAttributeMaxDynamicSharedMemorySize,
                         2 * (A_TILE + B_TILE));

    // 0: weight splits
    const int nsplit = 2 * CH * C + C * C;
    prep_split<<<(nsplit + 255) / 256, 256>>>(Wq, Wk, Wv, Wq_h, Wq_l, Wk_h, Wk_l, Wv_h, Wv_l);

    // 1: input transpose (Q,K bf16 split; V f16)
    transpose_all<<<dim3(N / 32, C / 32, 3 * B), 256>>>(
        Q, Kin, V, Qt_h, Qt_l, Kt_h, Kt_l, Vt, C, N, B);

    // 2: qt[n][ch] = Qt . Wq^T + bq[ch]  (bf16 split-3, split out)
    tgemm_kernel<<<dim3(CH / 256, N / 128, B), 256, TG_SMEM>>>(
        Qt_h, Qt_l, Wq_h, Wq_l, nullptr, qt_h, qt_l, bq,
        C, CH, (size_t)N * C, 0, (size_t)N * CH, F_SPLIT | F_BCOL);
    // 3: kt
    tgemm_kernel<<<dim3(CH / 256, N / 128, B), 256, TG_SMEM>>>(
        Kt_h, Kt_l, Wk_h, Wk_l, nullptr, kt_h, kt_l, bk,
        C, CH, (size_t)N * C, 0, (size_t)N * CH, F_SPLIT | F_BCOL);

    // 4: v[c][n] = Wv . Vt^T + bv[c]  (f16 2-pass, f16 single out)
    tgemm_h<1><<<dim3(N / 256, C / 128, B), 256, 2 * (2 * A_TILE + B_TILE)>>>(
        Wv_h, Wv_l, Vt, nullptr, v, bv, nullptr, nullptr,
        C, N, 0, (size_t)N * C, (size_t)C * N, 0, F_BROW);

    // 5 (profiled): e[n][m] = qt . kt^T  (bf16 split-3, f32 out)
    tgemm_kernel<<<dim3(N / 256, N / 128, B), 256, TG_SMEM>>>(
        qt_h, qt_l, kt_h, kt_l, e, nullptr, nullptr, nullptr,
        CH, N, (size_t)N * CH, (size_t)N * CH, (size_t)N * N, 0);

    // 6: attention = softmax_m(e) -> single f16
    softmax_row<<<dim3(N, B), 256>>>(e, a, N);

    // 7: out[c][n] = gamma * (v . attn^T) + V   (f16 1-pass)
    tgemm_h<0><<<dim3(N / 256, C / 128, B), 256, 2 * (A_TILE + B_TILE)>>>(
        v, nullptr, a, out, nullptr, nullptr, V, gamma,
        N, N, (size_t)C * N, (size_t)N * N, (size_t)C * N, (size_t)C * N, F_RES);
}